// round 1
// baseline (speedup 1.0000x reference)
#include <cuda_runtime.h>
#include <math.h>

#define DIM      128
#define NCENT    30
#define DIME     158
#define N_NODES  50000
#define N_EDGES  800000
#define N_CONV   3
#define EVOCAB   500
#define LDA      132
#define TILE     128
#define NTHREADS 256

// Scratch (device globals: allocation-free rule)
__device__ __align__(256) float g_H[(size_t)N_NODES * DIM];   // node features (updated in place)
__device__ __align__(256) float g_NP[(size_t)N_NODES * DIM];  // per-node node_path for current layer
__device__ __align__(256) float g_T1[512 * DIM];              // per-edge-type partial (emb @ We1[:128] + be1)

// ---------------------------------------------------------------------------
// helpers
// ---------------------------------------------------------------------------
__device__ __forceinline__ void zero_acc(float acc[8][8]) {
#pragma unroll
    for (int i = 0; i < 8; ++i)
#pragma unroll
        for (int j = 0; j < 8; ++j) acc[i][j] = 0.f;
}

// acc[8][8] += As[r0..r0+7][k] * W[k][c0..c0+7], k = 0..K-1
// As: smem row-major with leading dim LD; W: global [K][DIM] row-major.
template <int K, int LD>
__device__ __forceinline__ void gemm_frag(const float* __restrict__ As,
                                          const float* __restrict__ W,
                                          int r0, int c0, float acc[8][8]) {
#pragma unroll 2
    for (int k = 0; k < K; ++k) {
        float a[8];
#pragma unroll
        for (int i = 0; i < 8; ++i) a[i] = As[(r0 + i) * LD + k];
        float4 w0 = __ldg((const float4*)(W + k * DIM + c0));
        float4 w1 = __ldg((const float4*)(W + k * DIM + c0 + 4));
        float w[8] = {w0.x, w0.y, w0.z, w0.w, w1.x, w1.y, w1.z, w1.w};
#pragma unroll
        for (int i = 0; i < 8; ++i) {
#pragma unroll
            for (int j = 0; j < 8; ++j) acc[i][j] = fmaf(a[i], w[j], acc[i][j]);
        }
    }
}

__device__ __forceinline__ void store_bias_tile(float* __restrict__ Cs, int r0, int c0,
                                                const float acc[8][8],
                                                const float* __restrict__ bias, bool relu) {
    float4 b0 = __ldg((const float4*)(bias + c0));
    float4 b1 = __ldg((const float4*)(bias + c0 + 4));
    float bb[8] = {b0.x, b0.y, b0.z, b0.w, b1.x, b1.y, b1.z, b1.w};
#pragma unroll
    for (int i = 0; i < 8; ++i) {
        float v[8];
#pragma unroll
        for (int j = 0; j < 8; ++j) {
            v[j] = acc[i][j] + bb[j];
            if (relu) v[j] = fmaxf(v[j], 0.f);
        }
        *(float4*)&Cs[(r0 + i) * LDA + c0]     = make_float4(v[0], v[1], v[2], v[3]);
        *(float4*)&Cs[(r0 + i) * LDA + c0 + 4] = make_float4(v[4], v[5], v[6], v[7]);
    }
}

__device__ __forceinline__ void red_add_v4(float* p, float a, float b, float c, float d) {
    asm volatile("red.global.add.v4.f32 [%0], {%1, %2, %3, %4};"
                 :: "l"(p), "f"(a), "f"(b), "f"(c), "f"(d) : "memory");
}

// ---------------------------------------------------------------------------
// kernels
// ---------------------------------------------------------------------------
__global__ void k_zero(float* out, int n) {
    int i = blockIdx.x * blockDim.x + threadIdx.x;
    if (i < n) out[i] = 0.f;
}

// h = node_emb[node_types]
__global__ void k_embed(const int* __restrict__ nt, const float* __restrict__ emb) {
    int idx = blockIdx.x * blockDim.x + threadIdx.x;  // over N_NODES*32 float4s
    if (idx < N_NODES * 32) {
        int n = idx >> 5, q = idx & 31;
        ((float4*)g_H)[(size_t)n * 32 + q] =
            __ldg(((const float4*)emb) + (size_t)nt[n] * 32 + q);
    }
}

// T1[t] = edge_emb[t] @ We1[:128] + be1   (per layer)
__global__ __launch_bounds__(NTHREADS) void k_t1(const float* __restrict__ edge_emb,
                                                 const float* __restrict__ We1,
                                                 const float* __restrict__ be1) {
    extern __shared__ __align__(16) float smem[];
    float* As = smem;
    const int tid = threadIdx.x;
    const int t0b = blockIdx.x * TILE;
    for (int idx = tid; idx < TILE * 32; idx += NTHREADS) {
        int r = idx >> 5, q = idx & 31;
        int row = t0b + r;
        float4 v = make_float4(0.f, 0.f, 0.f, 0.f);
        if (row < EVOCAB) v = __ldg(((const float4*)edge_emb) + (size_t)row * 32 + q);
        *(float4*)&As[r * LDA + q * 4] = v;
    }
    __syncthreads();
    const int tr = tid >> 4, tc = tid & 15;
    const int r0 = tr * 8, c0 = tc * 8;
    float acc[8][8];
    zero_acc(acc);
    gemm_frag<DIM, LDA>(As, We1, r0, c0, acc);
    float4 b0 = __ldg((const float4*)(be1 + c0));
    float4 b1 = __ldg((const float4*)(be1 + c0 + 4));
    float bb[8] = {b0.x, b0.y, b0.z, b0.w, b1.x, b1.y, b1.z, b1.w};
#pragma unroll
    for (int i = 0; i < 8; ++i) {
        int row = t0b + r0 + i;
        if (row < EVOCAB) {
            float* tp = g_T1 + (size_t)row * DIM + c0;
            *(float4*)tp       = make_float4(acc[i][0] + bb[0], acc[i][1] + bb[1],
                                             acc[i][2] + bb[2], acc[i][3] + bb[3]);
            *(float4*)(tp + 4) = make_float4(acc[i][4] + bb[4], acc[i][5] + bb[5],
                                             acc[i][6] + bb[6], acc[i][7] + bb[7]);
        }
    }
}

// NP = relu(H @ Wn1 + bn1) @ Wn2 + bn2   (per node, per layer)
__global__ __launch_bounds__(NTHREADS) void k_nodepath(const float* __restrict__ Wn1,
                                                       const float* __restrict__ bn1,
                                                       const float* __restrict__ Wn2,
                                                       const float* __restrict__ bn2) {
    extern __shared__ __align__(16) float smem[];
    float* As = smem;
    float* Bs = As + TILE * LDA;
    const int tid = threadIdx.x;
    const int n0 = blockIdx.x * TILE;
    const int tr = tid >> 4, tc = tid & 15;
    const int r0 = tr * 8, c0 = tc * 8;

    for (int idx = tid; idx < TILE * 32; idx += NTHREADS) {
        int r = idx >> 5, q = idx & 31;
        int n = n0 + r;
        float4 v = make_float4(0.f, 0.f, 0.f, 0.f);
        if (n < N_NODES) v = *(const float4*)(g_H + (size_t)n * DIM + q * 4);
        *(float4*)&As[r * LDA + q * 4] = v;
    }
    __syncthreads();

    float acc[8][8];
    zero_acc(acc);
    gemm_frag<DIM, LDA>(As, Wn1, r0, c0, acc);
    store_bias_tile(Bs, r0, c0, acc, bn1, true);
    __syncthreads();

    zero_acc(acc);
    gemm_frag<DIM, LDA>(Bs, Wn2, r0, c0, acc);
    float4 b0 = __ldg((const float4*)(bn2 + c0));
    float4 b1 = __ldg((const float4*)(bn2 + c0 + 4));
    float bb[8] = {b0.x, b0.y, b0.z, b0.w, b1.x, b1.y, b1.z, b1.w};
#pragma unroll
    for (int i = 0; i < 8; ++i) {
        int n = n0 + r0 + i;
        if (n < N_NODES) {
            float* np = g_NP + (size_t)n * DIM + c0;
            *(float4*)np       = make_float4(acc[i][0] + bb[0], acc[i][1] + bb[1],
                                             acc[i][2] + bb[2], acc[i][3] + bb[3]);
            *(float4*)(np + 4) = make_float4(acc[i][4] + bb[4], acc[i][5] + bb[5],
                                             acc[i][6] + bb[6], acc[i][7] + bb[7]);
        }
    }
}

// Fused per-edge message kernel:
//   P1 = relu(T1[type] + rbf(d) @ We1_rbf)
//   EP = P1 @ We2 + be2
//   M  = tanh((NP[src] * EP) @ Wc + bc)
//   H[dst] += M   (vector red)
__global__ __launch_bounds__(NTHREADS) void k_edge(const int* __restrict__ etype,
                                                   const int* __restrict__ esrc,
                                                   const int* __restrict__ edst,
                                                   const float* __restrict__ dist,
                                                   const float* __restrict__ We1rbf,
                                                   const float* __restrict__ We2,
                                                   const float* __restrict__ be2,
                                                   const float* __restrict__ Wc,
                                                   const float* __restrict__ bc) {
    extern __shared__ __align__(16) float smem[];
    float* As = smem;                 // [128][132]
    float* Bs = As + TILE * LDA;      // [128][132]
    float* Rs = Bs + TILE * LDA;      // [128][33]
    int* s_type = (int*)(Rs + TILE * 33);
    int* s_src  = s_type + TILE;
    int* s_dst  = s_src + TILE;

    const int tid = threadIdx.x;
    const int e0 = blockIdx.x * TILE;
    const int tr = tid >> 4, tc = tid & 15;
    const int r0 = tr * 8, c0 = tc * 8;

    if (tid < TILE) {
        s_type[tid] = etype[e0 + tid];
        s_src[tid]  = esrc[e0 + tid];
        s_dst[tid]  = edst[e0 + tid];
    }
    // RBF expansion: rbf_j = exp(-(d - c_j)^2 / gap), gap = 10/29, c_j = j*10/29
    for (int idx = tid; idx < TILE * NCENT; idx += NTHREADS) {
        int r = idx / NCENT, j = idx - r * NCENT;
        float d = __ldg(&dist[e0 + r]);
        float cj = (10.0f / 29.0f) * (float)j;
        float t = d - cj;
        Rs[r * 33 + j] = expf(-t * t * (29.0f / 10.0f));
    }
    __syncthreads();

    float acc[8][8];

    // P1 = relu(rbf @ We1_rbf + T1[type])  -> As
    zero_acc(acc);
    gemm_frag<NCENT, 33>(Rs, We1rbf, r0, c0, acc);
#pragma unroll
    for (int i = 0; i < 8; ++i) {
        int t = s_type[r0 + i];
        const float* tp = g_T1 + (size_t)t * DIM + c0;
        float4 t0 = *(const float4*)tp;
        float4 t1 = *(const float4*)(tp + 4);
        float4 v0, v1;
        v0.x = fmaxf(acc[i][0] + t0.x, 0.f);
        v0.y = fmaxf(acc[i][1] + t0.y, 0.f);
        v0.z = fmaxf(acc[i][2] + t0.z, 0.f);
        v0.w = fmaxf(acc[i][3] + t0.w, 0.f);
        v1.x = fmaxf(acc[i][4] + t1.x, 0.f);
        v1.y = fmaxf(acc[i][5] + t1.y, 0.f);
        v1.z = fmaxf(acc[i][6] + t1.z, 0.f);
        v1.w = fmaxf(acc[i][7] + t1.w, 0.f);
        *(float4*)&As[(r0 + i) * LDA + c0]     = v0;
        *(float4*)&As[(r0 + i) * LDA + c0 + 4] = v1;
    }
    __syncthreads();

    // EP = P1 @ We2 + be2  -> Bs
    zero_acc(acc);
    gemm_frag<DIM, LDA>(As, We2, r0, c0, acc);
    store_bias_tile(Bs, r0, c0, acc, be2, false);
    __syncthreads();

    // As <- NP[src]
    for (int idx = tid; idx < TILE * 32; idx += NTHREADS) {
        int r = idx >> 5, q = idx & 31;
        *(float4*)&As[r * LDA + q * 4] =
            *(const float4*)(g_NP + (size_t)s_src[r] * DIM + q * 4);
    }
    __syncthreads();

    // As <- As * Bs (elementwise product)
    for (int idx = tid; idx < TILE * 32; idx += NTHREADS) {
        int r = idx >> 5, q = idx & 31;
        float4 a = *(float4*)&As[r * LDA + q * 4];
        float4 b = *(float4*)&Bs[r * LDA + q * 4];
        a.x *= b.x; a.y *= b.y; a.z *= b.z; a.w *= b.w;
        *(float4*)&As[r * LDA + q * 4] = a;
    }
    __syncthreads();

    // M = tanh(prod @ Wc + bc); H[dst] += M
    zero_acc(acc);
    gemm_frag<DIM, LDA>(As, Wc, r0, c0, acc);
    float4 b0 = __ldg((const float4*)(bc + c0));
    float4 b1 = __ldg((const float4*)(bc + c0 + 4));
    float bb[8] = {b0.x, b0.y, b0.z, b0.w, b1.x, b1.y, b1.z, b1.w};
#pragma unroll
    for (int i = 0; i < 8; ++i) {
        float* hp = g_H + (size_t)s_dst[r0 + i] * DIM + c0;
        float m[8];
#pragma unroll
        for (int j = 0; j < 8; ++j) m[j] = tanhf(acc[i][j] + bb[j]);
        red_add_v4(hp, m[0], m[1], m[2], m[3]);
        red_add_v4(hp + 4, m[4], m[5], m[6], m[7]);
    }
}

// hr = relu(H @ Wr1 + br1) @ Wr2 + br2 ; out[graph_ids[n]] += hr
__global__ __launch_bounds__(NTHREADS) void k_readout(const int* __restrict__ gids,
                                                      const float* __restrict__ Wr1,
                                                      const float* __restrict__ br1,
                                                      const float* __restrict__ Wr2,
                                                      const float* __restrict__ br2,
                                                      float* __restrict__ out) {
    extern __shared__ __align__(16) float smem[];
    float* As = smem;
    float* Bs = As + TILE * LDA;
    const int tid = threadIdx.x;
    const int n0 = blockIdx.x * TILE;
    const int tr = tid >> 4, tc = tid & 15;
    const int r0 = tr * 8, c0 = tc * 8;

    for (int idx = tid; idx < TILE * 32; idx += NTHREADS) {
        int r = idx >> 5, q = idx & 31;
        int n = n0 + r;
        float4 v = make_float4(0.f, 0.f, 0.f, 0.f);
        if (n < N_NODES) v = *(const float4*)(g_H + (size_t)n * DIM + q * 4);
        *(float4*)&As[r * LDA + q * 4] = v;
    }
    __syncthreads();

    float acc[8][8];
    zero_acc(acc);
    gemm_frag<DIM, LDA>(As, Wr1, r0, c0, acc);
    store_bias_tile(Bs, r0, c0, acc, br1, true);
    __syncthreads();

    if (tid < TILE) {
        int n = n0 + tid;
        if (n < N_NODES) {
            float s = __ldg(&br2[0]);
#pragma unroll 8
            for (int c = 0; c < DIM; c += 4) {
                float4 b = *(float4*)&Bs[tid * LDA + c];
                float4 w = __ldg((const float4*)(Wr2 + c));
                s += b.x * w.x + b.y * w.y + b.z * w.z + b.w * w.w;
            }
            atomicAdd(&out[gids[n]], s);
        }
    }
}

// ---------------------------------------------------------------------------
// launch
// ---------------------------------------------------------------------------
extern "C" void kernel_launch(void* const* d_in, const int* in_sizes, int n_in,
                              void* d_out, int out_size) {
    // first 6 inputs fixed; 16 weight tensors at the tail (robust to whether
    // the scalar n_graphs appears as an input)
    const int wb = n_in - 16;
    const int*   node_types = (const int*)d_in[0];
    const int*   edge_types = (const int*)d_in[1];
    const int*   src        = (const int*)d_in[2];
    const int*   dst        = (const int*)d_in[3];
    const int*   graph_ids  = (const int*)d_in[4];
    const float* distances  = (const float*)d_in[5];
    const float* node_emb = (const float*)d_in[wb + 0];
    const float* edge_emb = (const float*)d_in[wb + 1];
    const float* Wn1 = (const float*)d_in[wb + 2];
    const float* bn1 = (const float*)d_in[wb + 3];
    const float* Wn2 = (const float*)d_in[wb + 4];
    const float* bn2 = (const float*)d_in[wb + 5];
    const float* We1 = (const float*)d_in[wb + 6];
    const float* be1 = (const float*)d_in[wb + 7];
    const float* We2 = (const float*)d_in[wb + 8];
    const float* be2 = (const float*)d_in[wb + 9];
    const float* Wc  = (const float*)d_in[wb + 10];
    const float* bc  = (const float*)d_in[wb + 11];
    const float* Wr1 = (const float*)d_in[wb + 12];
    const float* br1 = (const float*)d_in[wb + 13];
    const float* Wr2 = (const float*)d_in[wb + 14];
    const float* br2 = (const float*)d_in[wb + 15];
    float* out = (float*)d_out;

    const int NSM = TILE * LDA * 2 * 4;                                   // 135168
    const int TSM = TILE * LDA * 4;                                       // 67584
    const int ESM = (TILE * LDA * 2 + TILE * 33) * 4 + 3 * TILE * 4;      // 153600

    cudaFuncSetAttribute(k_edge,     cudaFuncAttributeMaxDynamicSharedMemorySize, ESM);
    cudaFuncSetAttribute(k_nodepath, cudaFuncAttributeMaxDynamicSharedMemorySize, NSM);
    cudaFuncSetAttribute(k_t1,       cudaFuncAttributeMaxDynamicSharedMemorySize, TSM);
    cudaFuncSetAttribute(k_readout,  cudaFuncAttributeMaxDynamicSharedMemorySize, NSM);

    k_zero<<<1, 128>>>(out, out_size);
    k_embed<<<(N_NODES * 32 + 255) / 256, 256>>>(node_types, node_emb);

    for (int i = 0; i < N_CONV; ++i) {
        k_nodepath<<<(N_NODES + TILE - 1) / TILE, NTHREADS, NSM>>>(
            Wn1 + (size_t)i * DIM * DIM, bn1 + (size_t)i * DIM,
            Wn2 + (size_t)i * DIM * DIM, bn2 + (size_t)i * DIM);
        k_t1<<<(EVOCAB + TILE - 1) / TILE, NTHREADS, TSM>>>(
            edge_emb, We1 + (size_t)i * DIME * DIM, be1 + (size_t)i * DIM);
        k_edge<<<N_EDGES / TILE, NTHREADS, ESM>>>(
            edge_types, src, dst, distances,
            We1 + (size_t)i * DIME * DIM + (size_t)DIM * DIM,
            We2 + (size_t)i * DIM * DIM, be2 + (size_t)i * DIM,
            Wc + (size_t)i * DIM * DIM, bc + (size_t)i * DIM);
    }

    k_readout<<<(N_NODES + TILE - 1) / TILE, NTHREADS, NSM>>>(
        graph_ids, Wr1, br1, Wr2, br2, out);
}

// round 2
// speedup vs baseline: 1.7185x; 1.7185x over previous
#include <cuda_runtime.h>
#include <math.h>

#define DIM      128
#define NCENT    30
#define DIME     158
#define N_NODES  50000
#define N_EDGES  800000
#define N_CONV   3
#define EVOCAB   500
#define LDA      132
#define TILE     128
#define NTHREADS 256

// Scratch (device globals: allocation-free rule)
__device__ __align__(256) float g_H[(size_t)N_NODES * DIM];   // node features
__device__ __align__(256) float g_NP[(size_t)N_NODES * DIM];  // per-node node_path
__device__ __align__(256) float g_T1[(size_t)N_CONV * 512 * DIM]; // per-layer per-type partial

// ---------------------------------------------------------------------------
// helpers
// ---------------------------------------------------------------------------
__device__ __forceinline__ void zero_acc(float acc[8][8]) {
#pragma unroll
    for (int i = 0; i < 8; ++i)
#pragma unroll
        for (int j = 0; j < 8; ++j) acc[i][j] = 0.f;
}

// fast tanh via MUFU EX2/RCP: err ~1e-6, far below the 1e-3 gate
__device__ __forceinline__ float tanh_fast(float x) {
    float ax = fabsf(x);
    float e = __expf(-2.0f * ax);
    float t = __fdividef(1.0f - e, 1.0f + e);
    return copysignf(t, x);
}

// acc[8][8] += As[r0..r0+7][k] * W[k][c0..c0+7], k = 0..K-1 (KW = valid W rows)
// A loads are vectorized float4 over k (LD must be multiple of 4).
template <int K, int KW, int LD>
__device__ __forceinline__ void gemm_frag4(const float* __restrict__ As,
                                           const float* __restrict__ W,
                                           int r0, int c0, float acc[8][8]) {
#pragma unroll 2
    for (int k = 0; k < K; k += 4) {
        float4 a4[8];
#pragma unroll
        for (int i = 0; i < 8; ++i) a4[i] = *(const float4*)&As[(r0 + i) * LD + k];
        const float* a = (const float*)a4;
#pragma unroll
        for (int kk = 0; kk < 4; ++kk) {
            int kq = k + kk;
            float w[8];
            if (K == KW || kq < KW) {
                float4 w0 = __ldg((const float4*)(W + kq * DIM + c0));
                float4 w1 = __ldg((const float4*)(W + kq * DIM + c0 + 4));
                w[0] = w0.x; w[1] = w0.y; w[2] = w0.z; w[3] = w0.w;
                w[4] = w1.x; w[5] = w1.y; w[6] = w1.z; w[7] = w1.w;
            } else {
#pragma unroll
                for (int j = 0; j < 8; ++j) w[j] = 0.f;
            }
#pragma unroll
            for (int i = 0; i < 8; ++i)
#pragma unroll
                for (int j = 0; j < 8; ++j)
                    acc[i][j] = fmaf(a[i * 4 + kk], w[j], acc[i][j]);
        }
    }
}

__device__ __forceinline__ void store_bias_tile(float* __restrict__ Cs, int r0, int c0,
                                                const float acc[8][8],
                                                const float* __restrict__ bias, bool relu) {
    float4 b0 = __ldg((const float4*)(bias + c0));
    float4 b1 = __ldg((const float4*)(bias + c0 + 4));
    float bb[8] = {b0.x, b0.y, b0.z, b0.w, b1.x, b1.y, b1.z, b1.w};
#pragma unroll
    for (int i = 0; i < 8; ++i) {
        float v[8];
#pragma unroll
        for (int j = 0; j < 8; ++j) {
            v[j] = acc[i][j] + bb[j];
            if (relu) v[j] = fmaxf(v[j], 0.f);
        }
        *(float4*)&Cs[(r0 + i) * LDA + c0]     = make_float4(v[0], v[1], v[2], v[3]);
        *(float4*)&Cs[(r0 + i) * LDA + c0 + 4] = make_float4(v[4], v[5], v[6], v[7]);
    }
}

__device__ __forceinline__ void red_add_v4(float* p, float a, float b, float c, float d) {
    asm volatile("red.global.add.v4.f32 [%0], {%1, %2, %3, %4};"
                 :: "l"(p), "f"(a), "f"(b), "f"(c), "f"(d) : "memory");
}

// ---------------------------------------------------------------------------
// kernels
// ---------------------------------------------------------------------------
__global__ void k_zero(float* out, int n) {
    int i = blockIdx.x * blockDim.x + threadIdx.x;
    if (i < n) out[i] = 0.f;
}

__global__ void k_embed(const int* __restrict__ nt, const float* __restrict__ emb) {
    int idx = blockIdx.x * blockDim.x + threadIdx.x;
    if (idx < N_NODES * 32) {
        int n = idx >> 5, q = idx & 31;
        ((float4*)g_H)[(size_t)n * 32 + q] =
            __ldg(((const float4*)emb) + (size_t)nt[n] * 32 + q);
    }
}

// T1[L][t] = edge_emb[t] @ We1[L][:128] + be1[L]   — all layers in one launch
__global__ __launch_bounds__(NTHREADS) void k_t1(const float* __restrict__ edge_emb,
                                                 const float* __restrict__ We1_all,
                                                 const float* __restrict__ be1_all) {
    extern __shared__ __align__(16) float smem[];
    float* As = smem;
    const int tid = threadIdx.x;
    const int layer = blockIdx.y;
    const int t0b = blockIdx.x * TILE;
    const float* We1 = We1_all + (size_t)layer * DIME * DIM;
    const float* be1 = be1_all + (size_t)layer * DIM;
    float* T1 = g_T1 + (size_t)layer * 512 * DIM;

    for (int idx = tid; idx < TILE * 32; idx += NTHREADS) {
        int r = idx >> 5, q = idx & 31;
        int row = t0b + r;
        float4 v = make_float4(0.f, 0.f, 0.f, 0.f);
        if (row < EVOCAB) v = __ldg(((const float4*)edge_emb) + (size_t)row * 32 + q);
        *(float4*)&As[r * LDA + q * 4] = v;
    }
    __syncthreads();
    const int tr = tid >> 4, tc = tid & 15;
    const int r0 = tr * 8, c0 = tc * 8;
    float acc[8][8];
    zero_acc(acc);
    gemm_frag4<DIM, DIM, LDA>(As, We1, r0, c0, acc);
    float4 b0 = __ldg((const float4*)(be1 + c0));
    float4 b1 = __ldg((const float4*)(be1 + c0 + 4));
    float bb[8] = {b0.x, b0.y, b0.z, b0.w, b1.x, b1.y, b1.z, b1.w};
#pragma unroll
    for (int i = 0; i < 8; ++i) {
        int row = t0b + r0 + i;
        if (row < EVOCAB) {
            float* tp = T1 + (size_t)row * DIM + c0;
            *(float4*)tp       = make_float4(acc[i][0] + bb[0], acc[i][1] + bb[1],
                                             acc[i][2] + bb[2], acc[i][3] + bb[3]);
            *(float4*)(tp + 4) = make_float4(acc[i][4] + bb[4], acc[i][5] + bb[5],
                                             acc[i][6] + bb[6], acc[i][7] + bb[7]);
        }
    }
}

// NP = relu(H @ Wn1 + bn1) @ Wn2 + bn2
__global__ __launch_bounds__(NTHREADS) void k_nodepath(const float* __restrict__ Wn1,
                                                       const float* __restrict__ bn1,
                                                       const float* __restrict__ Wn2,
                                                       const float* __restrict__ bn2) {
    extern __shared__ __align__(16) float smem[];
    float* As = smem;
    float* Bs = As + TILE * LDA;
    const int tid = threadIdx.x;
    const int n0 = blockIdx.x * TILE;
    const int tr = tid >> 4, tc = tid & 15;
    const int r0 = tr * 8, c0 = tc * 8;

    for (int idx = tid; idx < TILE * 32; idx += NTHREADS) {
        int r = idx >> 5, q = idx & 31;
        int n = n0 + r;
        float4 v = make_float4(0.f, 0.f, 0.f, 0.f);
        if (n < N_NODES) v = *(const float4*)(g_H + (size_t)n * DIM + q * 4);
        *(float4*)&As[r * LDA + q * 4] = v;
    }
    __syncthreads();

    float acc[8][8];
    zero_acc(acc);
    gemm_frag4<DIM, DIM, LDA>(As, Wn1, r0, c0, acc);
    store_bias_tile(Bs, r0, c0, acc, bn1, true);
    __syncthreads();

    zero_acc(acc);
    gemm_frag4<DIM, DIM, LDA>(Bs, Wn2, r0, c0, acc);
    float4 b0 = __ldg((const float4*)(bn2 + c0));
    float4 b1 = __ldg((const float4*)(bn2 + c0 + 4));
    float bb[8] = {b0.x, b0.y, b0.z, b0.w, b1.x, b1.y, b1.z, b1.w};
#pragma unroll
    for (int i = 0; i < 8; ++i) {
        int n = n0 + r0 + i;
        if (n < N_NODES) {
            float* np = g_NP + (size_t)n * DIM + c0;
            *(float4*)np       = make_float4(acc[i][0] + bb[0], acc[i][1] + bb[1],
                                             acc[i][2] + bb[2], acc[i][3] + bb[3]);
            *(float4*)(np + 4) = make_float4(acc[i][4] + bb[4], acc[i][5] + bb[5],
                                             acc[i][6] + bb[6], acc[i][7] + bb[7]);
        }
    }
}

// Fused per-edge message kernel. smem: As[128][132] + Rs[128][32] + 3*128 ints
__global__ __launch_bounds__(NTHREADS, 2) void k_edge(const int* __restrict__ etype,
                                                      const int* __restrict__ esrc,
                                                      const int* __restrict__ edst,
                                                      const float* __restrict__ dist,
                                                      const float* __restrict__ We1rbf,
                                                      const float* __restrict__ We2,
                                                      const float* __restrict__ be2,
                                                      const float* __restrict__ Wc,
                                                      const float* __restrict__ bc,
                                                      int layer) {
    extern __shared__ __align__(16) float smem[];
    float* As = smem;                     // [128][132]
    float* Rs = As + TILE * LDA;          // [128][32]
    int* s_type = (int*)(Rs + TILE * 32);
    int* s_src  = s_type + TILE;
    int* s_dst  = s_src + TILE;

    const int tid = threadIdx.x;
    const int e0 = blockIdx.x * TILE;
    const int tr = tid >> 4, tc = tid & 15;
    const int r0 = tr * 8, c0 = tc * 8;
    const float* T1 = g_T1 + (size_t)layer * 512 * DIM;

    if (tid < TILE) {
        s_type[tid] = etype[e0 + tid];
        s_src[tid]  = esrc[e0 + tid];
        s_dst[tid]  = edst[e0 + tid];
    }
    // RBF: rbf_j = exp(-(d - c_j)^2 / gap), gap = 10/29; cols 30,31 zero-padded
    for (int idx = tid; idx < TILE * 32; idx += NTHREADS) {
        int r = idx >> 5, j = idx & 31;
        float v = 0.f;
        if (j < NCENT) {
            float d = __ldg(&dist[e0 + r]);
            float t = d - (10.0f / 29.0f) * (float)j;
            v = __expf(-t * t * (29.0f / 10.0f));
        }
        Rs[r * 32 + j] = v;
    }
    __syncthreads();

    float acc[8][8];

    // P1 = relu(rbf @ We1_rbf + T1[type])  -> As
    zero_acc(acc);
    gemm_frag4<32, NCENT, 32>(Rs, We1rbf, r0, c0, acc);
#pragma unroll
    for (int i = 0; i < 8; ++i) {
        int t = s_type[r0 + i];
        const float* tp = T1 + (size_t)t * DIM + c0;
        float4 t0 = *(const float4*)tp;
        float4 t1 = *(const float4*)(tp + 4);
        float4 v0, v1;
        v0.x = fmaxf(acc[i][0] + t0.x, 0.f);
        v0.y = fmaxf(acc[i][1] + t0.y, 0.f);
        v0.z = fmaxf(acc[i][2] + t0.z, 0.f);
        v0.w = fmaxf(acc[i][3] + t0.w, 0.f);
        v1.x = fmaxf(acc[i][4] + t1.x, 0.f);
        v1.y = fmaxf(acc[i][5] + t1.y, 0.f);
        v1.z = fmaxf(acc[i][6] + t1.z, 0.f);
        v1.w = fmaxf(acc[i][7] + t1.w, 0.f);
        *(float4*)&As[(r0 + i) * LDA + c0]     = v0;
        *(float4*)&As[(r0 + i) * LDA + c0 + 4] = v1;
    }
    __syncthreads();

    // EP = P1 @ We2 + be2; fold product with NP[src] in the epilogue (registers)
    zero_acc(acc);
    gemm_frag4<DIM, DIM, LDA>(As, We2, r0, c0, acc);
    {
        float4 b0 = __ldg((const float4*)(be2 + c0));
        float4 b1 = __ldg((const float4*)(be2 + c0 + 4));
        float bb[8] = {b0.x, b0.y, b0.z, b0.w, b1.x, b1.y, b1.z, b1.w};
#pragma unroll
        for (int i = 0; i < 8; ++i) {
            const float* np = g_NP + (size_t)s_src[r0 + i] * DIM + c0;
            float4 n0 = __ldg((const float4*)np);
            float4 n1 = __ldg((const float4*)(np + 4));
            acc[i][0] = (acc[i][0] + bb[0]) * n0.x;
            acc[i][1] = (acc[i][1] + bb[1]) * n0.y;
            acc[i][2] = (acc[i][2] + bb[2]) * n0.z;
            acc[i][3] = (acc[i][3] + bb[3]) * n0.w;
            acc[i][4] = (acc[i][4] + bb[4]) * n1.x;
            acc[i][5] = (acc[i][5] + bb[5]) * n1.y;
            acc[i][6] = (acc[i][6] + bb[6]) * n1.z;
            acc[i][7] = (acc[i][7] + bb[7]) * n1.w;
        }
    }
    __syncthreads();  // all reads of As (P1) complete
#pragma unroll
    for (int i = 0; i < 8; ++i) {
        *(float4*)&As[(r0 + i) * LDA + c0]     = make_float4(acc[i][0], acc[i][1], acc[i][2], acc[i][3]);
        *(float4*)&As[(r0 + i) * LDA + c0 + 4] = make_float4(acc[i][4], acc[i][5], acc[i][6], acc[i][7]);
    }
    __syncthreads();

    // M = tanh(prod @ Wc + bc); H[dst] += M
    zero_acc(acc);
    gemm_frag4<DIM, DIM, LDA>(As, Wc, r0, c0, acc);
    float4 b0 = __ldg((const float4*)(bc + c0));
    float4 b1 = __ldg((const float4*)(bc + c0 + 4));
    float bb[8] = {b0.x, b0.y, b0.z, b0.w, b1.x, b1.y, b1.z, b1.w};
#pragma unroll
    for (int i = 0; i < 8; ++i) {
        float* hp = g_H + (size_t)s_dst[r0 + i] * DIM + c0;
        float m[8];
#pragma unroll
        for (int j = 0; j < 8; ++j) m[j] = tanh_fast(acc[i][j] + bb[j]);
        red_add_v4(hp, m[0], m[1], m[2], m[3]);
        red_add_v4(hp + 4, m[4], m[5], m[6], m[7]);
    }
}

// hr = relu(H @ Wr1 + br1) @ Wr2 + br2 ; out[graph_ids[n]] += hr
__global__ __launch_bounds__(NTHREADS) void k_readout(const int* __restrict__ gids,
                                                      const float* __restrict__ Wr1,
                                                      const float* __restrict__ br1,
                                                      const float* __restrict__ Wr2,
                                                      const float* __restrict__ br2,
                                                      float* __restrict__ out) {
    extern __shared__ __align__(16) float smem[];
    float* As = smem;
    float* Bs = As + TILE * LDA;
    const int tid = threadIdx.x;
    const int n0 = blockIdx.x * TILE;
    const int tr = tid >> 4, tc = tid & 15;
    const int r0 = tr * 8, c0 = tc * 8;

    for (int idx = tid; idx < TILE * 32; idx += NTHREADS) {
        int r = idx >> 5, q = idx & 31;
        int n = n0 + r;
        float4 v = make_float4(0.f, 0.f, 0.f, 0.f);
        if (n < N_NODES) v = *(const float4*)(g_H + (size_t)n * DIM + q * 4);
        *(float4*)&As[r * LDA + q * 4] = v;
    }
    __syncthreads();

    float acc[8][8];
    zero_acc(acc);
    gemm_frag4<DIM, DIM, LDA>(As, Wr1, r0, c0, acc);
    store_bias_tile(Bs, r0, c0, acc, br1, true);
    __syncthreads();

    if (tid < TILE) {
        int n = n0 + tid;
        if (n < N_NODES) {
            float s = __ldg(&br2[0]);
#pragma unroll 8
            for (int c = 0; c < DIM; c += 4) {
                float4 b = *(float4*)&Bs[tid * LDA + c];
                float4 w = __ldg((const float4*)(Wr2 + c));
                s += b.x * w.x + b.y * w.y + b.z * w.z + b.w * w.w;
            }
            atomicAdd(&out[gids[n]], s);
        }
    }
}

// ---------------------------------------------------------------------------
// launch
// ---------------------------------------------------------------------------
extern "C" void kernel_launch(void* const* d_in, const int* in_sizes, int n_in,
                              void* d_out, int out_size) {
    const int wb = n_in - 16;
    const int*   node_types = (const int*)d_in[0];
    const int*   edge_types = (const int*)d_in[1];
    const int*   src        = (const int*)d_in[2];
    const int*   dst        = (const int*)d_in[3];
    const int*   graph_ids  = (const int*)d_in[4];
    const float* distances  = (const float*)d_in[5];
    const float* node_emb = (const float*)d_in[wb + 0];
    const float* edge_emb = (const float*)d_in[wb + 1];
    const float* Wn1 = (const float*)d_in[wb + 2];
    const float* bn1 = (const float*)d_in[wb + 3];
    const float* Wn2 = (const float*)d_in[wb + 4];
    const float* bn2 = (const float*)d_in[wb + 5];
    const float* We1 = (const float*)d_in[wb + 6];
    const float* be1 = (const float*)d_in[wb + 7];
    const float* We2 = (const float*)d_in[wb + 8];
    const float* be2 = (const float*)d_in[wb + 9];
    const float* Wc  = (const float*)d_in[wb + 10];
    const float* bc  = (const float*)d_in[wb + 11];
    const float* Wr1 = (const float*)d_in[wb + 12];
    const float* br1 = (const float*)d_in[wb + 13];
    const float* Wr2 = (const float*)d_in[wb + 14];
    const float* br2 = (const float*)d_in[wb + 15];
    float* out = (float*)d_out;

    const int NSM = TILE * LDA * 2 * 4;                            // 135168
    const int TSM = TILE * LDA * 4;                                // 67584
    const int ESM = (TILE * LDA + TILE * 32) * 4 + 3 * TILE * 4;   // 85504

    cudaFuncSetAttribute(k_edge,     cudaFuncAttributeMaxDynamicSharedMemorySize, ESM);
    cudaFuncSetAttribute(k_nodepath, cudaFuncAttributeMaxDynamicSharedMemorySize, NSM);
    cudaFuncSetAttribute(k_t1,       cudaFuncAttributeMaxDynamicSharedMemorySize, TSM);
    cudaFuncSetAttribute(k_readout,  cudaFuncAttributeMaxDynamicSharedMemorySize, NSM);

    k_zero<<<1, 128>>>(out, out_size);
    k_embed<<<(N_NODES * 32 + 255) / 256, 256>>>(node_types, node_emb);
    k_t1<<<dim3(4, 3), NTHREADS, TSM>>>(edge_emb, We1, be1);  // all 3 layers

    for (int i = 0; i < N_CONV; ++i) {
        k_nodepath<<<(N_NODES + TILE - 1) / TILE, NTHREADS, NSM>>>(
            Wn1 + (size_t)i * DIM * DIM, bn1 + (size_t)i * DIM,
            Wn2 + (size_t)i * DIM * DIM, bn2 + (size_t)i * DIM);
        k_edge<<<N_EDGES / TILE, NTHREADS, ESM>>>(
            edge_types, src, dst, distances,
            We1 + (size_t)i * DIME * DIM + (size_t)DIM * DIM,
            We2 + (size_t)i * DIM * DIM, be2 + (size_t)i * DIM,
            Wc + (size_t)i * DIM * DIM, bc + (size_t)i * DIM, i);
    }

    k_readout<<<(N_NODES + TILE - 1) / TILE, NTHREADS, NSM>>>(
        graph_ids, Wr1, br1, Wr2, br2, out);
}

// round 5
// speedup vs baseline: 3.6056x; 2.0981x over previous
#include <cuda_runtime.h>
#include <math.h>
#include <stdint.h>

#define DIM      128
#define NCENT    30
#define DIME     158
#define N_NODES  50000
#define N_EDGES  800000
#define N_CONV   3
#define EVOCAB   500
#define LDA      132
#define TILE     128
#define NTHREADS 256
#define N_TILES  (N_EDGES / TILE)   // 6250

// One shared extern smem symbol for the whole TU (char; cast per kernel)
extern __shared__ __align__(1024) char smem_raw[];

// Scratch (device globals: allocation-free rule)
__device__ __align__(256) float g_H[(size_t)N_NODES * DIM];
__device__ __align__(256) float g_NP[(size_t)N_NODES * DIM];
__device__ __align__(256) float g_T1[(size_t)N_CONV * 512 * DIM];

// ---------------------------------------------------------------------------
// helpers
// ---------------------------------------------------------------------------
__device__ __forceinline__ float to_tf32(float x) {
    float r; asm("cvt.rna.tf32.f32 %0, %1;" : "=f"(r) : "f"(x)); return r;
}

__device__ __forceinline__ float tanh_fast(float x) {
    float ax = fabsf(x);
    float e = __expf(-2.0f * ax);
    float t = __fdividef(1.0f - e, 1.0f + e);
    return copysignf(t, x);
}

__device__ __forceinline__ void zero_acc8(float acc[8][8]) {
#pragma unroll
    for (int i = 0; i < 8; ++i)
#pragma unroll
        for (int j = 0; j < 8; ++j) acc[i][j] = 0.f;
}

__device__ __forceinline__ void red_add_v2(float* p, float a, float b) {
    asm volatile("red.global.add.v2.f32 [%0], {%1, %2};"
                 :: "l"(p), "f"(a), "f"(b) : "memory");
}

// m16n8k8 tf32 HMMA: D = A*B + D (fp32 accum). a: 4 regs, b: 2 regs.
__device__ __forceinline__ void mma1688(float c[4], const uint32_t a[4],
                                        uint32_t b0, uint32_t b1) {
    asm volatile(
        "mma.sync.aligned.m16n8k8.row.col.f32.tf32.tf32.f32 "
        "{%0,%1,%2,%3}, {%4,%5,%6,%7}, {%8,%9}, {%0,%1,%2,%3};"
        : "+f"(c[0]), "+f"(c[1]), "+f"(c[2]), "+f"(c[3])
        : "r"(a[0]), "r"(a[1]), "r"(a[2]), "r"(a[3]), "r"(b0), "r"(b1));
}

// Warp GEMM: acc[2][8][4] += A[warp 32 rows][K] * W[K][warp 64 cols]
// As_u: stride 132 (conflict-free A frags). W_u: stride 136 (conflict-free B frags).
template <int KSTEPS>
__device__ __forceinline__ void hgemm(const uint32_t* __restrict__ As_u,
                                      const uint32_t* __restrict__ W_u,
                                      int wr, int wc, int gid, int t4,
                                      float acc[2][8][4]) {
#pragma unroll 2
    for (int ks = 0; ks < KSTEPS; ++ks) {
        const int k0 = ks * 8;
        uint32_t a[2][4];
#pragma unroll
        for (int mb = 0; mb < 2; ++mb) {
            const int r = wr * 32 + mb * 16 + gid;
            a[mb][0] = As_u[r * 132 + k0 + t4];
            a[mb][1] = As_u[(r + 8) * 132 + k0 + t4];
            a[mb][2] = As_u[r * 132 + k0 + t4 + 4];
            a[mb][3] = As_u[(r + 8) * 132 + k0 + t4 + 4];
        }
#pragma unroll
        for (int nb = 0; nb < 8; ++nb) {
            const int n = wc * 64 + nb * 8 + gid;
            const uint32_t b0 = W_u[(k0 + t4) * 136 + n];
            const uint32_t b1 = W_u[(k0 + t4 + 4) * 136 + n];
            mma1688(acc[0][nb], a[0], b0, b1);
            mma1688(acc[1][nb], a[1], b0, b1);
        }
    }
}

__device__ __forceinline__ void zacc(float acc[2][8][4]) {
#pragma unroll
    for (int m = 0; m < 2; ++m)
#pragma unroll
        for (int n = 0; n < 8; ++n)
#pragma unroll
            for (int j = 0; j < 4; ++j) acc[m][n][j] = 0.f;
}

// ---------------------------------------------------------------------------
// FFMA helpers for the small kernels
// ---------------------------------------------------------------------------
template <int K, int KW, int LD>
__device__ __forceinline__ void gemm_frag4(const float* __restrict__ As,
                                           const float* __restrict__ W,
                                           int r0, int c0, float acc[8][8]) {
#pragma unroll 2
    for (int k = 0; k < K; k += 4) {
        float4 a4[8];
#pragma unroll
        for (int i = 0; i < 8; ++i) a4[i] = *(const float4*)&As[(r0 + i) * LD + k];
        const float* a = (const float*)a4;
#pragma unroll
        for (int kk = 0; kk < 4; ++kk) {
            int kq = k + kk;
            float w[8];
            if (K == KW || kq < KW) {
                float4 w0 = __ldg((const float4*)(W + kq * DIM + c0));
                float4 w1 = __ldg((const float4*)(W + kq * DIM + c0 + 4));
                w[0] = w0.x; w[1] = w0.y; w[2] = w0.z; w[3] = w0.w;
                w[4] = w1.x; w[5] = w1.y; w[6] = w1.z; w[7] = w1.w;
            } else {
#pragma unroll
                for (int j = 0; j < 8; ++j) w[j] = 0.f;
            }
#pragma unroll
            for (int i = 0; i < 8; ++i)
#pragma unroll
                for (int j = 0; j < 8; ++j)
                    acc[i][j] = fmaf(a[i * 4 + kk], w[j], acc[i][j]);
        }
    }
}

__device__ __forceinline__ void store_bias_tile(float* __restrict__ Cs, int r0, int c0,
                                                const float acc[8][8],
                                                const float* __restrict__ bias, bool relu) {
    float4 b0 = __ldg((const float4*)(bias + c0));
    float4 b1 = __ldg((const float4*)(bias + c0 + 4));
    float bb[8] = {b0.x, b0.y, b0.z, b0.w, b1.x, b1.y, b1.z, b1.w};
#pragma unroll
    for (int i = 0; i < 8; ++i) {
        float v[8];
#pragma unroll
        for (int j = 0; j < 8; ++j) {
            v[j] = acc[i][j] + bb[j];
            if (relu) v[j] = fmaxf(v[j], 0.f);
        }
        *(float4*)&Cs[(r0 + i) * LDA + c0]     = make_float4(v[0], v[1], v[2], v[3]);
        *(float4*)&Cs[(r0 + i) * LDA + c0 + 4] = make_float4(v[4], v[5], v[6], v[7]);
    }
}

// ---------------------------------------------------------------------------
// small kernels
// ---------------------------------------------------------------------------
__global__ void k_zero(float* out, int n) {
    int i = blockIdx.x * blockDim.x + threadIdx.x;
    if (i < n) out[i] = 0.f;
}

__global__ void k_embed(const int* __restrict__ nt, const float* __restrict__ emb) {
    int idx = blockIdx.x * blockDim.x + threadIdx.x;
    if (idx < N_NODES * 32) {
        int n = idx >> 5, q = idx & 31;
        ((float4*)g_H)[(size_t)n * 32 + q] =
            __ldg(((const float4*)emb) + (size_t)nt[n] * 32 + q);
    }
}

__global__ __launch_bounds__(NTHREADS) void k_t1(const float* __restrict__ edge_emb,
                                                 const float* __restrict__ We1_all,
                                                 const float* __restrict__ be1_all) {
    float* As = (float*)smem_raw;
    const int tid = threadIdx.x;
    const int layer = blockIdx.y;
    const int t0b = blockIdx.x * TILE;
    const float* We1 = We1_all + (size_t)layer * DIME * DIM;
    const float* be1 = be1_all + (size_t)layer * DIM;
    float* T1 = g_T1 + (size_t)layer * 512 * DIM;

    for (int idx = tid; idx < TILE * 32; idx += NTHREADS) {
        int r = idx >> 5, q = idx & 31;
        int row = t0b + r;
        float4 v = make_float4(0.f, 0.f, 0.f, 0.f);
        if (row < EVOCAB) v = __ldg(((const float4*)edge_emb) + (size_t)row * 32 + q);
        *(float4*)&As[r * LDA + q * 4] = v;
    }
    __syncthreads();
    const int tr = tid >> 4, tc = tid & 15;
    const int r0 = tr * 8, c0 = tc * 8;
    float acc[8][8];
    zero_acc8(acc);
    gemm_frag4<DIM, DIM, LDA>(As, We1, r0, c0, acc);
    float4 b0 = __ldg((const float4*)(be1 + c0));
    float4 b1 = __ldg((const float4*)(be1 + c0 + 4));
    float bb[8] = {b0.x, b0.y, b0.z, b0.w, b1.x, b1.y, b1.z, b1.w};
#pragma unroll
    for (int i = 0; i < 8; ++i) {
        int row = t0b + r0 + i;
        if (row < EVOCAB) {
            float* tp = T1 + (size_t)row * DIM + c0;
            *(float4*)tp       = make_float4(acc[i][0] + bb[0], acc[i][1] + bb[1],
                                             acc[i][2] + bb[2], acc[i][3] + bb[3]);
            *(float4*)(tp + 4) = make_float4(acc[i][4] + bb[4], acc[i][5] + bb[5],
                                             acc[i][6] + bb[6], acc[i][7] + bb[7]);
        }
    }
}

__global__ __launch_bounds__(NTHREADS) void k_nodepath(const float* __restrict__ Wn1,
                                                       const float* __restrict__ bn1,
                                                       const float* __restrict__ Wn2,
                                                       const float* __restrict__ bn2) {
    float* As = (float*)smem_raw;
    float* Bs = As + TILE * LDA;
    const int tid = threadIdx.x;
    const int n0 = blockIdx.x * TILE;
    const int tr = tid >> 4, tc = tid & 15;
    const int r0 = tr * 8, c0 = tc * 8;

    for (int idx = tid; idx < TILE * 32; idx += NTHREADS) {
        int r = idx >> 5, q = idx & 31;
        int n = n0 + r;
        float4 v = make_float4(0.f, 0.f, 0.f, 0.f);
        if (n < N_NODES) v = *(const float4*)(g_H + (size_t)n * DIM + q * 4);
        *(float4*)&As[r * LDA + q * 4] = v;
    }
    __syncthreads();

    float acc[8][8];
    zero_acc8(acc);
    gemm_frag4<DIM, DIM, LDA>(As, Wn1, r0, c0, acc);
    store_bias_tile(Bs, r0, c0, acc, bn1, true);
    __syncthreads();

    zero_acc8(acc);
    gemm_frag4<DIM, DIM, LDA>(Bs, Wn2, r0, c0, acc);
    float4 b0 = __ldg((const float4*)(bn2 + c0));
    float4 b1 = __ldg((const float4*)(bn2 + c0 + 4));
    float bb[8] = {b0.x, b0.y, b0.z, b0.w, b1.x, b1.y, b1.z, b1.w};
#pragma unroll
    for (int i = 0; i < 8; ++i) {
        int n = n0 + r0 + i;
        if (n < N_NODES) {
            float* np = g_NP + (size_t)n * DIM + c0;
            *(float4*)np       = make_float4(acc[i][0] + bb[0], acc[i][1] + bb[1],
                                             acc[i][2] + bb[2], acc[i][3] + bb[3]);
            *(float4*)(np + 4) = make_float4(acc[i][4] + bb[4], acc[i][5] + bb[5],
                                             acc[i][6] + bb[6], acc[i][7] + bb[7]);
        }
    }
}

__global__ __launch_bounds__(NTHREADS) void k_readout(const int* __restrict__ gids,
                                                      const float* __restrict__ Wr1,
                                                      const float* __restrict__ br1,
                                                      const float* __restrict__ Wr2,
                                                      const float* __restrict__ br2,
                                                      float* __restrict__ out) {
    float* As = (float*)smem_raw;
    float* Bs = As + TILE * LDA;
    const int tid = threadIdx.x;
    const int n0 = blockIdx.x * TILE;
    const int tr = tid >> 4, tc = tid & 15;
    const int r0 = tr * 8, c0 = tc * 8;

    for (int idx = tid; idx < TILE * 32; idx += NTHREADS) {
        int r = idx >> 5, q = idx & 31;
        int n = n0 + r;
        float4 v = make_float4(0.f, 0.f, 0.f, 0.f);
        if (n < N_NODES) v = *(const float4*)(g_H + (size_t)n * DIM + q * 4);
        *(float4*)&As[r * LDA + q * 4] = v;
    }
    __syncthreads();

    float acc[8][8];
    zero_acc8(acc);
    gemm_frag4<DIM, DIM, LDA>(As, Wr1, r0, c0, acc);
    store_bias_tile(Bs, r0, c0, acc, br1, true);
    __syncthreads();

    if (tid < TILE) {
        int n = n0 + tid;
        if (n < N_NODES) {
            float s = __ldg(&br2[0]);
#pragma unroll 8
            for (int c = 0; c < DIM; c += 4) {
                float4 b = *(float4*)&Bs[tid * LDA + c];
                float4 w = __ldg((const float4*)(Wr2 + c));
                s += b.x * w.x + b.y * w.y + b.z * w.z + b.w * w.w;
            }
            atomicAdd(&out[gids[n]], s);
        }
    }
}

// ---------------------------------------------------------------------------
// Persistent tf32 mma.sync edge kernel
// SMEM (floats): As[128*132]=16896 | W2[128*136]=17408 | WC[128*136]=17408 |
//                WR[32*136]=4352  | idx 3*128 ints    -> 56448 floats = 225792 B
// ---------------------------------------------------------------------------
#define F_AS  0
#define F_W2  16896
#define F_WC  34304
#define F_WR  51712
#define F_IDX 56064
#define ESMEM 225792

__global__ __launch_bounds__(NTHREADS, 1) void k_edge_hmma(const int* __restrict__ etype,
                                                           const int* __restrict__ esrc,
                                                           const int* __restrict__ edst,
                                                           const float* __restrict__ dist,
                                                           const float* __restrict__ We1rbf,
                                                           const float* __restrict__ We2,
                                                           const float* __restrict__ be2,
                                                           const float* __restrict__ Wc,
                                                           const float* __restrict__ bc,
                                                           int layer) {
    float* smf = (float*)smem_raw;
    float* Asf = smf + F_AS;
    uint32_t* As_u = (uint32_t*)Asf;
    uint32_t* W2_u = (uint32_t*)(smf + F_W2);
    uint32_t* WC_u = (uint32_t*)(smf + F_WC);
    uint32_t* WR_u = (uint32_t*)(smf + F_WR);
    int* s_type = (int*)(smf + F_IDX);
    int* s_src  = s_type + TILE;
    int* s_dst  = s_src + TILE;

    const int tid = threadIdx.x;
    const int wid = tid >> 5;
    const int lane = tid & 31;
    const int gid = lane >> 2;   // 0..7
    const int t4  = lane & 3;    // 0..3
    const int wr  = wid & 3;     // row block (32 rows)
    const int wc  = wid >> 2;    // col block (64 cols)

    // --- one-time weight staging (tf32, stride 136) ---
    for (int idx = tid; idx < 128 * 128; idx += NTHREADS) {
        int k = idx >> 7, n = idx & 127;
        ((float*)W2_u)[k * 136 + n] = to_tf32(__ldg(&We2[k * DIM + n]));
        ((float*)WC_u)[k * 136 + n] = to_tf32(__ldg(&Wc[k * DIM + n]));
    }
    for (int idx = tid; idx < 32 * 128; idx += NTHREADS) {
        int k = idx >> 7, n = idx & 127;
        ((float*)WR_u)[k * 136 + n] = (k < NCENT) ? to_tf32(__ldg(&We1rbf[k * DIM + n])) : 0.f;
    }

    // per-thread bias fragments (fixed cols for all tiles)
    float2 vbe2[8], vbc[8];
#pragma unroll
    for (int nb = 0; nb < 8; ++nb) {
        int col = wc * 64 + nb * 8 + t4 * 2;
        vbe2[nb] = __ldg((const float2*)(be2 + col));
        vbc[nb]  = __ldg((const float2*)(bc + col));
    }
    const float* T1 = g_T1 + (size_t)layer * 512 * DIM;
    __syncthreads();

    float acc[2][8][4];

    for (int tile = blockIdx.x; tile < N_TILES; tile += gridDim.x) {
        const int e0 = tile * TILE;
        if (tid < TILE) {
            s_type[tid] = __ldg(&etype[e0 + tid]);
            s_src[tid]  = __ldg(&esrc[e0 + tid]);
            s_dst[tid]  = __ldg(&edst[e0 + tid]);
        }
        // rbf -> As cols [0,32) (tf32; cols >= NCENT zero)
        {
            const int r = tid >> 1, half = tid & 1;
            const float d = __ldg(&dist[e0 + r]);
#pragma unroll
            for (int jj = 0; jj < 4; ++jj) {
                float4 v;
                float* vv = (float*)&v;
#pragma unroll
                for (int u = 0; u < 4; ++u) {
                    int j = half * 16 + jj * 4 + u;
                    float rv = 0.f;
                    if (j < NCENT) {
                        float t = d - (10.0f / 29.0f) * (float)j;
                        rv = to_tf32(__expf(-t * t * (29.0f / 10.0f)));
                    }
                    vv[u] = rv;
                }
                *(float4*)(Asf + r * 132 + half * 16 + jj * 4) = v;
            }
        }
        __syncthreads();

        // GEMM0: rbf(128x32) @ WR(32x128)
        zacc(acc);
        hgemm<4>(As_u, WR_u, wr, wc, gid, t4, acc);
        __syncthreads();  // all A reads of rbf complete

        // epilogue0: P1 = tf32(relu(acc + T1[type])) -> As
#pragma unroll
        for (int mb = 0; mb < 2; ++mb)
#pragma unroll
            for (int h = 0; h < 2; ++h) {
                const int row = wr * 32 + mb * 16 + gid + h * 8;
                const float* t1p = T1 + (size_t)s_type[row] * DIM;
#pragma unroll
                for (int nb = 0; nb < 8; ++nb) {
                    const int col = wc * 64 + nb * 8 + t4 * 2;
                    float2 tv = __ldg((const float2*)(t1p + col));
                    float v0 = to_tf32(fmaxf(acc[mb][nb][2 * h + 0] + tv.x, 0.f));
                    float v1 = to_tf32(fmaxf(acc[mb][nb][2 * h + 1] + tv.y, 0.f));
                    *(float2*)(Asf + row * 132 + col) = make_float2(v0, v1);
                }
            }
        __syncthreads();

        // GEMM1: P1 @ We2
        zacc(acc);
        hgemm<16>(As_u, W2_u, wr, wc, gid, t4, acc);
        __syncthreads();  // all A reads of P1 complete

        // epilogue1: P2 = tf32((acc + be2) * NP[src]) -> As
#pragma unroll
        for (int mb = 0; mb < 2; ++mb)
#pragma unroll
            for (int h = 0; h < 2; ++h) {
                const int row = wr * 32 + mb * 16 + gid + h * 8;
                const float* npp = g_NP + (size_t)s_src[row] * DIM;
#pragma unroll
                for (int nb = 0; nb < 8; ++nb) {
                    const int col = wc * 64 + nb * 8 + t4 * 2;
                    float2 np = __ldg((const float2*)(npp + col));
                    float v0 = to_tf32((acc[mb][nb][2 * h + 0] + vbe2[nb].x) * np.x);
                    float v1 = to_tf32((acc[mb][nb][2 * h + 1] + vbe2[nb].y) * np.y);
                    *(float2*)(Asf + row * 132 + col) = make_float2(v0, v1);
                }
            }
        __syncthreads();

        // GEMM2: P2 @ Wc
        zacc(acc);
        hgemm<16>(As_u, WC_u, wr, wc, gid, t4, acc);

        // epilogue2: m = tanh(acc + bc); H[dst] += m
#pragma unroll
        for (int mb = 0; mb < 2; ++mb)
#pragma unroll
            for (int h = 0; h < 2; ++h) {
                const int row = wr * 32 + mb * 16 + gid + h * 8;
                float* hp = g_H + (size_t)s_dst[row] * DIM;
#pragma unroll
                for (int nb = 0; nb < 8; ++nb) {
                    const int col = wc * 64 + nb * 8 + t4 * 2;
                    float m0 = tanh_fast(acc[mb][nb][2 * h + 0] + vbc[nb].x);
                    float m1 = tanh_fast(acc[mb][nb][2 * h + 1] + vbc[nb].y);
                    red_add_v2(hp + col, m0, m1);
                }
            }
        __syncthreads();  // protect As / s_* before next tile
    }
}

// ---------------------------------------------------------------------------
// launch
// ---------------------------------------------------------------------------
extern "C" void kernel_launch(void* const* d_in, const int* in_sizes, int n_in,
                              void* d_out, int out_size) {
    const int wb = n_in - 16;
    const int*   node_types = (const int*)d_in[0];
    const int*   edge_types = (const int*)d_in[1];
    const int*   src        = (const int*)d_in[2];
    const int*   dst        = (const int*)d_in[3];
    const int*   graph_ids  = (const int*)d_in[4];
    const float* distances  = (const float*)d_in[5];
    const float* node_emb = (const float*)d_in[wb + 0];
    const float* edge_emb = (const float*)d_in[wb + 1];
    const float* Wn1 = (const float*)d_in[wb + 2];
    const float* bn1 = (const float*)d_in[wb + 3];
    const float* Wn2 = (const float*)d_in[wb + 4];
    const float* bn2 = (const float*)d_in[wb + 5];
    const float* We1 = (const float*)d_in[wb + 6];
    const float* be1 = (const float*)d_in[wb + 7];
    const float* We2 = (const float*)d_in[wb + 8];
    const float* be2 = (const float*)d_in[wb + 9];
    const float* Wc  = (const float*)d_in[wb + 10];
    const float* bc  = (const float*)d_in[wb + 11];
    const float* Wr1 = (const float*)d_in[wb + 12];
    const float* br1 = (const float*)d_in[wb + 13];
    const float* Wr2 = (const float*)d_in[wb + 14];
    const float* br2 = (const float*)d_in[wb + 15];
    float* out = (float*)d_out;

    const int NSM = TILE * LDA * 2 * 4;
    const int TSM = TILE * LDA * 4;

    cudaFuncSetAttribute(k_edge_hmma, cudaFuncAttributeMaxDynamicSharedMemorySize, ESMEM);
    cudaFuncSetAttribute(k_nodepath,  cudaFuncAttributeMaxDynamicSharedMemorySize, NSM);
    cudaFuncSetAttribute(k_t1,        cudaFuncAttributeMaxDynamicSharedMemorySize, TSM);
    cudaFuncSetAttribute(k_readout,   cudaFuncAttributeMaxDynamicSharedMemorySize, NSM);

    k_zero<<<1, 128>>>(out, out_size);
    k_embed<<<(N_NODES * 32 + 255) / 256, 256>>>(node_types, node_emb);
    k_t1<<<dim3(4, 3), NTHREADS, TSM>>>(edge_emb, We1, be1);

    for (int i = 0; i < N_CONV; ++i) {
        k_nodepath<<<(N_NODES + TILE - 1) / TILE, NTHREADS, NSM>>>(
            Wn1 + (size_t)i * DIM * DIM, bn1 + (size_t)i * DIM,
            Wn2 + (size_t)i * DIM * DIM, bn2 + (size_t)i * DIM);
        k_edge_hmma<<<148, NTHREADS, ESMEM>>>(
            edge_types, src, dst, distances,
            We1 + (size_t)i * DIME * DIM + (size_t)DIM * DIM,
            We2 + (size_t)i * DIM * DIM, be2 + (size_t)i * DIM,
            Wc + (size_t)i * DIM * DIM, bc + (size_t)i * DIM, i);
    }

    k_readout<<<(N_NODES + TILE - 1) / TILE, NTHREADS, NSM>>>(
        graph_ids, Wr1, br1, Wr2, br2, out);
}

// round 6
// speedup vs baseline: 4.0116x; 1.1126x over previous
#include <cuda_runtime.h>
#include <math.h>
#include <stdint.h>

#define DIM      128
#define NCENT    30
#define DIME     158
#define N_NODES  50000
#define N_EDGES  800000
#define N_CONV   3
#define EVOCAB   500
#define LDA      132
#define TILE     128
#define NTHREADS 256
#define N_TILES  (N_EDGES / TILE)     // 6250
#define N_NTILES ((N_NODES + 127) / 128)  // 391

// One shared extern smem symbol for the whole TU (char; cast per kernel)
extern __shared__ __align__(1024) char smem_raw[];

// Scratch (device globals: allocation-free rule)
__device__ __align__(256) float g_H[(size_t)N_NODES * DIM];
__device__ __align__(256) float g_NP[(size_t)N_NODES * DIM];
__device__ __align__(256) float g_T1[(size_t)N_CONV * 512 * DIM];

// ---------------------------------------------------------------------------
// helpers
// ---------------------------------------------------------------------------
__device__ __forceinline__ float to_tf32(float x) {
    float r; asm("cvt.rna.tf32.f32 %0, %1;" : "=f"(r) : "f"(x)); return r;
}

__device__ __forceinline__ float tanh_fast(float x) {
    float ax = fabsf(x);
    float e = __expf(-2.0f * ax);
    float t = __fdividef(1.0f - e, 1.0f + e);
    return copysignf(t, x);
}

__device__ __forceinline__ void red_add_v2(float* p, float a, float b) {
    asm volatile("red.global.add.v2.f32 [%0], {%1, %2};"
                 :: "l"(p), "f"(a), "f"(b) : "memory");
}

// m16n8k8 tf32 HMMA
__device__ __forceinline__ void mma1688(float c[4], const uint32_t a[4],
                                        uint32_t b0, uint32_t b1) {
    asm volatile(
        "mma.sync.aligned.m16n8k8.row.col.f32.tf32.tf32.f32 "
        "{%0,%1,%2,%3}, {%4,%5,%6,%7}, {%8,%9}, {%0,%1,%2,%3};"
        : "+f"(c[0]), "+f"(c[1]), "+f"(c[2]), "+f"(c[3])
        : "r"(a[0]), "r"(a[1]), "r"(a[2]), "r"(a[3]), "r"(b0), "r"(b1));
}

// 32-row (mb=2) warp GEMM: acc[2][8][4] += A[32r][K] * W[K][64c]
template <int KSTEPS>
__device__ __forceinline__ void hgemm2(const uint32_t* __restrict__ As_u,
                                       const uint32_t* __restrict__ W_u,
                                       int wr, int wc, int gid, int t4,
                                       float acc[2][8][4]) {
#pragma unroll 2
    for (int ks = 0; ks < KSTEPS; ++ks) {
        const int k0 = ks * 8;
        uint32_t a[2][4];
#pragma unroll
        for (int mb = 0; mb < 2; ++mb) {
            const int r = wr * 32 + mb * 16 + gid;
            a[mb][0] = As_u[r * 132 + k0 + t4];
            a[mb][1] = As_u[(r + 8) * 132 + k0 + t4];
            a[mb][2] = As_u[r * 132 + k0 + t4 + 4];
            a[mb][3] = As_u[(r + 8) * 132 + k0 + t4 + 4];
        }
#pragma unroll
        for (int nb = 0; nb < 8; ++nb) {
            const int n = wc * 64 + nb * 8 + gid;
            const uint32_t b0 = W_u[(k0 + t4) * 136 + n];
            const uint32_t b1 = W_u[(k0 + t4 + 4) * 136 + n];
            mma1688(acc[0][nb], a[0], b0, b1);
            mma1688(acc[1][nb], a[1], b0, b1);
        }
    }
}

// 16-row (mb=1) warp GEMM: acc[8][4] += A[16r][K] * W[K][64c]
template <int KSTEPS>
__device__ __forceinline__ void hgemm1(const uint32_t* __restrict__ As_u,
                                       const uint32_t* __restrict__ W_u,
                                       int wr, int wc, int gid, int t4,
                                       float acc[8][4]) {
#pragma unroll 2
    for (int ks = 0; ks < KSTEPS; ++ks) {
        const int k0 = ks * 8;
        uint32_t a[4];
        const int r = wr * 16 + gid;
        a[0] = As_u[r * 132 + k0 + t4];
        a[1] = As_u[(r + 8) * 132 + k0 + t4];
        a[2] = As_u[r * 132 + k0 + t4 + 4];
        a[3] = As_u[(r + 8) * 132 + k0 + t4 + 4];
#pragma unroll
        for (int nb = 0; nb < 8; ++nb) {
            const int n = wc * 64 + nb * 8 + gid;
            const uint32_t b0 = W_u[(k0 + t4) * 136 + n];
            const uint32_t b1 = W_u[(k0 + t4 + 4) * 136 + n];
            mma1688(acc[nb], a, b0, b1);
        }
    }
}

__device__ __forceinline__ void zacc2(float acc[2][8][4]) {
#pragma unroll
    for (int m = 0; m < 2; ++m)
#pragma unroll
        for (int n = 0; n < 8; ++n)
#pragma unroll
            for (int j = 0; j < 4; ++j) acc[m][n][j] = 0.f;
}
__device__ __forceinline__ void zacc1(float acc[8][4]) {
#pragma unroll
    for (int n = 0; n < 8; ++n)
#pragma unroll
        for (int j = 0; j < 4; ++j) acc[n][j] = 0.f;
}

// ---------------------------------------------------------------------------
// FFMA helpers (k_t1 only)
// ---------------------------------------------------------------------------
__device__ __forceinline__ void zero_acc8(float acc[8][8]) {
#pragma unroll
    for (int i = 0; i < 8; ++i)
#pragma unroll
        for (int j = 0; j < 8; ++j) acc[i][j] = 0.f;
}

template <int K, int KW, int LD>
__device__ __forceinline__ void gemm_frag4(const float* __restrict__ As,
                                           const float* __restrict__ W,
                                           int r0, int c0, float acc[8][8]) {
#pragma unroll 2
    for (int k = 0; k < K; k += 4) {
        float4 a4[8];
#pragma unroll
        for (int i = 0; i < 8; ++i) a4[i] = *(const float4*)&As[(r0 + i) * LD + k];
        const float* a = (const float*)a4;
#pragma unroll
        for (int kk = 0; kk < 4; ++kk) {
            int kq = k + kk;
            float w[8];
            if (K == KW || kq < KW) {
                float4 w0 = __ldg((const float4*)(W + kq * DIM + c0));
                float4 w1 = __ldg((const float4*)(W + kq * DIM + c0 + 4));
                w[0] = w0.x; w[1] = w0.y; w[2] = w0.z; w[3] = w0.w;
                w[4] = w1.x; w[5] = w1.y; w[6] = w1.z; w[7] = w1.w;
            } else {
#pragma unroll
                for (int j = 0; j < 8; ++j) w[j] = 0.f;
            }
#pragma unroll
            for (int i = 0; i < 8; ++i)
#pragma unroll
                for (int j = 0; j < 8; ++j)
                    acc[i][j] = fmaf(a[i * 4 + kk], w[j], acc[i][j]);
        }
    }
}

// ---------------------------------------------------------------------------
// small kernels
// ---------------------------------------------------------------------------
__global__ void k_zero(float* out, int n) {
    int i = blockIdx.x * blockDim.x + threadIdx.x;
    if (i < n) out[i] = 0.f;
}

__global__ void k_embed(const int* __restrict__ nt, const float* __restrict__ emb) {
    int idx = blockIdx.x * blockDim.x + threadIdx.x;
    if (idx < N_NODES * 32) {
        int n = idx >> 5, q = idx & 31;
        ((float4*)g_H)[(size_t)n * 32 + q] =
            __ldg(((const float4*)emb) + (size_t)nt[n] * 32 + q);
    }
}

__global__ __launch_bounds__(NTHREADS) void k_t1(const float* __restrict__ edge_emb,
                                                 const float* __restrict__ We1_all,
                                                 const float* __restrict__ be1_all) {
    float* As = (float*)smem_raw;
    const int tid = threadIdx.x;
    const int layer = blockIdx.y;
    const int t0b = blockIdx.x * TILE;
    const float* We1 = We1_all + (size_t)layer * DIME * DIM;
    const float* be1 = be1_all + (size_t)layer * DIM;
    float* T1 = g_T1 + (size_t)layer * 512 * DIM;

    for (int idx = tid; idx < TILE * 32; idx += NTHREADS) {
        int r = idx >> 5, q = idx & 31;
        int row = t0b + r;
        float4 v = make_float4(0.f, 0.f, 0.f, 0.f);
        if (row < EVOCAB) v = __ldg(((const float4*)edge_emb) + (size_t)row * 32 + q);
        *(float4*)&As[r * LDA + q * 4] = v;
    }
    __syncthreads();
    const int tr = tid >> 4, tc = tid & 15;
    const int r0 = tr * 8, c0 = tc * 8;
    float acc[8][8];
    zero_acc8(acc);
    gemm_frag4<DIM, DIM, LDA>(As, We1, r0, c0, acc);
    float4 b0 = __ldg((const float4*)(be1 + c0));
    float4 b1 = __ldg((const float4*)(be1 + c0 + 4));
    float bb[8] = {b0.x, b0.y, b0.z, b0.w, b1.x, b1.y, b1.z, b1.w};
#pragma unroll
    for (int i = 0; i < 8; ++i) {
        int row = t0b + r0 + i;
        if (row < EVOCAB) {
            float* tp = T1 + (size_t)row * DIM + c0;
            *(float4*)tp       = make_float4(acc[i][0] + bb[0], acc[i][1] + bb[1],
                                             acc[i][2] + bb[2], acc[i][3] + bb[3]);
            *(float4*)(tp + 4) = make_float4(acc[i][4] + bb[4], acc[i][5] + bb[5],
                                             acc[i][6] + bb[6], acc[i][7] + bb[7]);
        }
    }
}

// ---------------------------------------------------------------------------
// Persistent HMMA node-path: NP = relu(H@Wn1+bn1)@Wn2+bn2
// smem floats: As 16896 | W1 17408 | W2 17408 = 51712 -> 206848 B
// ---------------------------------------------------------------------------
#define NP_AS 0
#define NP_W1 16896
#define NP_W2 34304
#define NPSMEM 206848

__global__ __launch_bounds__(NTHREADS, 1) void k_nodepath_hmma(const float* __restrict__ Wn1,
                                                               const float* __restrict__ bn1,
                                                               const float* __restrict__ Wn2,
                                                               const float* __restrict__ bn2) {
    float* smf = (float*)smem_raw;
    float* Asf = smf + NP_AS;
    uint32_t* As_u = (uint32_t*)Asf;
    uint32_t* W1_u = (uint32_t*)(smf + NP_W1);
    uint32_t* W2_u = (uint32_t*)(smf + NP_W2);

    const int tid = threadIdx.x;
    const int wid = tid >> 5, lane = tid & 31;
    const int gid = lane >> 2, t4 = lane & 3;
    const int wr = wid & 3, wc = wid >> 2;

    for (int idx = tid; idx < 128 * 128; idx += NTHREADS) {
        int k = idx >> 7, n = idx & 127;
        ((float*)W1_u)[k * 136 + n] = to_tf32(__ldg(&Wn1[k * DIM + n]));
        ((float*)W2_u)[k * 136 + n] = to_tf32(__ldg(&Wn2[k * DIM + n]));
    }
    __syncthreads();

    float acc[2][8][4];

    for (int tile = blockIdx.x; tile < N_NTILES; tile += gridDim.x) {
        const int n0 = tile * TILE;
        // load H tile -> tf32 -> As
        for (int idx = tid; idx < TILE * 32; idx += NTHREADS) {
            int r = idx >> 5, q = idx & 31;
            int n = n0 + r;
            float4 v = make_float4(0.f, 0.f, 0.f, 0.f);
            if (n < N_NODES) {
                v = *(const float4*)(g_H + (size_t)n * DIM + q * 4);
                v.x = to_tf32(v.x); v.y = to_tf32(v.y);
                v.z = to_tf32(v.z); v.w = to_tf32(v.w);
            }
            *(float4*)&Asf[r * 132 + q * 4] = v;
        }
        __syncthreads();

        zacc2(acc);
        hgemm2<16>(As_u, W1_u, wr, wc, gid, t4, acc);
        __syncthreads();

        // relu(acc + bn1) -> tf32 -> As
#pragma unroll
        for (int mb = 0; mb < 2; ++mb)
#pragma unroll
            for (int h = 0; h < 2; ++h) {
                const int row = wr * 32 + mb * 16 + gid + h * 8;
#pragma unroll
                for (int nb = 0; nb < 8; ++nb) {
                    const int col = wc * 64 + nb * 8 + t4 * 2;
                    float2 bb = __ldg((const float2*)(bn1 + col));
                    float v0 = to_tf32(fmaxf(acc[mb][nb][2 * h + 0] + bb.x, 0.f));
                    float v1 = to_tf32(fmaxf(acc[mb][nb][2 * h + 1] + bb.y, 0.f));
                    *(float2*)(Asf + row * 132 + col) = make_float2(v0, v1);
                }
            }
        __syncthreads();

        zacc2(acc);
        hgemm2<16>(As_u, W2_u, wr, wc, gid, t4, acc);

        // NP = acc + bn2 (guarded)
#pragma unroll
        for (int mb = 0; mb < 2; ++mb)
#pragma unroll
            for (int h = 0; h < 2; ++h) {
                const int row = wr * 32 + mb * 16 + gid + h * 8;
                const int n = n0 + row;
                if (n < N_NODES) {
                    float* np = g_NP + (size_t)n * DIM;
#pragma unroll
                    for (int nb = 0; nb < 8; ++nb) {
                        const int col = wc * 64 + nb * 8 + t4 * 2;
                        float2 bb = __ldg((const float2*)(bn2 + col));
                        *(float2*)(np + col) = make_float2(acc[mb][nb][2 * h + 0] + bb.x,
                                                           acc[mb][nb][2 * h + 1] + bb.y);
                    }
                }
            }
        __syncthreads();
    }
}

// ---------------------------------------------------------------------------
// Persistent HMMA readout: hr = relu(H@Wr1+br1)@Wr2+br2; out[gid] += hr
// smem floats: As 16896 | W1 17408 = 34304 -> 137216 B
// ---------------------------------------------------------------------------
#define RO_AS 0
#define RO_W1 16896
#define ROSMEM 137216

__global__ __launch_bounds__(NTHREADS, 1) void k_readout_hmma(const int* __restrict__ gids,
                                                              const float* __restrict__ Wr1,
                                                              const float* __restrict__ br1,
                                                              const float* __restrict__ Wr2,
                                                              const float* __restrict__ br2,
                                                              float* __restrict__ out) {
    float* smf = (float*)smem_raw;
    float* Asf = smf + RO_AS;
    uint32_t* As_u = (uint32_t*)Asf;
    uint32_t* W1_u = (uint32_t*)(smf + RO_W1);

    const int tid = threadIdx.x;
    const int wid = tid >> 5, lane = tid & 31;
    const int gid = lane >> 2, t4 = lane & 3;
    const int wr = wid & 3, wc = wid >> 2;

    for (int idx = tid; idx < 128 * 128; idx += NTHREADS) {
        int k = idx >> 7, n = idx & 127;
        ((float*)W1_u)[k * 136 + n] = to_tf32(__ldg(&Wr1[k * DIM + n]));
    }
    __syncthreads();

    float acc[2][8][4];

    for (int tile = blockIdx.x; tile < N_NTILES; tile += gridDim.x) {
        const int n0 = tile * TILE;
        for (int idx = tid; idx < TILE * 32; idx += NTHREADS) {
            int r = idx >> 5, q = idx & 31;
            int n = n0 + r;
            float4 v = make_float4(0.f, 0.f, 0.f, 0.f);
            if (n < N_NODES) {
                v = *(const float4*)(g_H + (size_t)n * DIM + q * 4);
                v.x = to_tf32(v.x); v.y = to_tf32(v.y);
                v.z = to_tf32(v.z); v.w = to_tf32(v.w);
            }
            *(float4*)&Asf[r * 132 + q * 4] = v;
        }
        __syncthreads();

        zacc2(acc);
        hgemm2<16>(As_u, W1_u, wr, wc, gid, t4, acc);
        __syncthreads();

        // relu(acc + br1) -> As (fp32)
#pragma unroll
        for (int mb = 0; mb < 2; ++mb)
#pragma unroll
            for (int h = 0; h < 2; ++h) {
                const int row = wr * 32 + mb * 16 + gid + h * 8;
#pragma unroll
                for (int nb = 0; nb < 8; ++nb) {
                    const int col = wc * 64 + nb * 8 + t4 * 2;
                    float2 bb = __ldg((const float2*)(br1 + col));
                    *(float2*)(Asf + row * 132 + col) =
                        make_float2(fmaxf(acc[mb][nb][2 * h + 0] + bb.x, 0.f),
                                    fmaxf(acc[mb][nb][2 * h + 1] + bb.y, 0.f));
                }
            }
        __syncthreads();

        if (tid < TILE) {
            int n = n0 + tid;
            if (n < N_NODES) {
                float s = __ldg(&br2[0]);
#pragma unroll 8
                for (int c = 0; c < DIM; c += 4) {
                    float4 b = *(float4*)&Asf[tid * 132 + c];
                    float4 w = __ldg((const float4*)(Wr2 + c));
                    s += b.x * w.x + b.y * w.y + b.z * w.z + b.w * w.w;
                }
                atomicAdd(&out[__ldg(&gids[n])], s);
            }
        }
        __syncthreads();
    }
}

// ---------------------------------------------------------------------------
// Persistent tf32 mma.sync edge kernel — 512 threads, 16 warps (8 wr x 2 wc),
// register prefetch of T1/NP gathers overlapped with MMA.
// SMEM floats: As 16896 | W2 17408 | WC 17408 | WR 4352 | idx 384 -> 225792 B
// ---------------------------------------------------------------------------
#define F_AS  0
#define F_W2  16896
#define F_WC  34304
#define F_WR  51712
#define F_IDX 56064
#define ESMEM 225792
#define ETHREADS 512

__global__ __launch_bounds__(ETHREADS, 1) void k_edge_hmma(const int* __restrict__ etype,
                                                           const int* __restrict__ esrc,
                                                           const int* __restrict__ edst,
                                                           const float* __restrict__ dist,
                                                           const float* __restrict__ We1rbf,
                                                           const float* __restrict__ We2,
                                                           const float* __restrict__ be2,
                                                           const float* __restrict__ Wc,
                                                           const float* __restrict__ bc,
                                                           int layer) {
    float* smf = (float*)smem_raw;
    float* Asf = smf + F_AS;
    uint32_t* As_u = (uint32_t*)Asf;
    uint32_t* W2_u = (uint32_t*)(smf + F_W2);
    uint32_t* WC_u = (uint32_t*)(smf + F_WC);
    uint32_t* WR_u = (uint32_t*)(smf + F_WR);
    int* s_type = (int*)(smf + F_IDX);
    int* s_src  = s_type + TILE;
    int* s_dst  = s_src + TILE;

    const int tid = threadIdx.x;
    const int wid = tid >> 5;
    const int lane = tid & 31;
    const int gid = lane >> 2;   // 0..7
    const int t4  = lane & 3;    // 0..3
    const int wr  = wid & 7;     // row block (16 rows)
    const int wc  = wid >> 3;    // col block (64 cols)

    // --- one-time weight staging (tf32, stride 136) ---
    for (int idx = tid; idx < 128 * 128; idx += ETHREADS) {
        int k = idx >> 7, n = idx & 127;
        ((float*)W2_u)[k * 136 + n] = to_tf32(__ldg(&We2[k * DIM + n]));
        ((float*)WC_u)[k * 136 + n] = to_tf32(__ldg(&Wc[k * DIM + n]));
    }
    for (int idx = tid; idx < 32 * 128; idx += ETHREADS) {
        int k = idx >> 7, n = idx & 127;
        ((float*)WR_u)[k * 136 + n] = (k < NCENT) ? to_tf32(__ldg(&We1rbf[k * DIM + n])) : 0.f;
    }
    const float* T1 = g_T1 + (size_t)layer * 512 * DIM;
    __syncthreads();

    float acc[8][4];
    float2 pf[2][8];

    for (int tile = blockIdx.x; tile < N_TILES; tile += gridDim.x) {
        const int e0 = tile * TILE;
        if (tid < TILE) {
            s_type[tid] = __ldg(&etype[e0 + tid]);
            s_src[tid]  = __ldg(&esrc[e0 + tid]);
            s_dst[tid]  = __ldg(&edst[e0 + tid]);
        }
        // rbf -> As cols [0,32): 4 threads per row, 8 cols each
        {
            const int r = tid >> 2, q4 = tid & 3;
            const float d = __ldg(&dist[e0 + r]);
#pragma unroll
            for (int jj = 0; jj < 2; ++jj) {
                float4 v;
                float* vv = (float*)&v;
#pragma unroll
                for (int u = 0; u < 4; ++u) {
                    int j = q4 * 8 + jj * 4 + u;
                    float rv = 0.f;
                    if (j < NCENT) {
                        float t = d - (10.0f / 29.0f) * (float)j;
                        rv = to_tf32(__expf(-t * t * (29.0f / 10.0f)));
                    }
                    vv[u] = rv;
                }
                *(float4*)(Asf + r * 132 + q4 * 8 + jj * 4) = v;
            }
        }
        __syncthreads();

        // prefetch T1[type] rows (overlaps GEMM0 MMA)
#pragma unroll
        for (int h = 0; h < 2; ++h) {
            const int row = wr * 16 + gid + h * 8;
            const float* t1p = T1 + (size_t)s_type[row] * DIM + wc * 64 + t4 * 2;
#pragma unroll
            for (int nb = 0; nb < 8; ++nb)
                pf[h][nb] = __ldg((const float2*)(t1p + nb * 8));
        }

        // GEMM0: rbf(128x32) @ WR(32x128)
        zacc1(acc);
        hgemm1<4>(As_u, WR_u, wr, wc, gid, t4, acc);
        __syncthreads();  // all A reads of rbf complete

        // epilogue0: P1 = tf32(relu(acc + T1)) -> As
#pragma unroll
        for (int h = 0; h < 2; ++h) {
            const int row = wr * 16 + gid + h * 8;
#pragma unroll
            for (int nb = 0; nb < 8; ++nb) {
                const int col = wc * 64 + nb * 8 + t4 * 2;
                float v0 = to_tf32(fmaxf(acc[nb][2 * h + 0] + pf[h][nb].x, 0.f));
                float v1 = to_tf32(fmaxf(acc[nb][2 * h + 1] + pf[h][nb].y, 0.f));
                *(float2*)(Asf + row * 132 + col) = make_float2(v0, v1);
            }
        }
        __syncthreads();

        // prefetch NP[src] rows (overlaps GEMM1 MMA)
#pragma unroll
        for (int h = 0; h < 2; ++h) {
            const int row = wr * 16 + gid + h * 8;
            const float* npp = g_NP + (size_t)s_src[row] * DIM + wc * 64 + t4 * 2;
#pragma unroll
            for (int nb = 0; nb < 8; ++nb)
                pf[h][nb] = __ldg((const float2*)(npp + nb * 8));
        }

        // GEMM1: P1 @ We2
        zacc1(acc);
        hgemm1<16>(As_u, W2_u, wr, wc, gid, t4, acc);
        __syncthreads();  // all A reads of P1 complete

        // epilogue1: P2 = tf32((acc + be2) * NP) -> As
#pragma unroll
        for (int h = 0; h < 2; ++h) {
            const int row = wr * 16 + gid + h * 8;
#pragma unroll
            for (int nb = 0; nb < 8; ++nb) {
                const int col = wc * 64 + nb * 8 + t4 * 2;
                float2 bb = __ldg((const float2*)(be2 + col));
                float v0 = to_tf32((acc[nb][2 * h + 0] + bb.x) * pf[h][nb].x);
                float v1 = to_tf32((acc[nb][2 * h + 1] + bb.y) * pf[h][nb].y);
                *(float2*)(Asf + row * 132 + col) = make_float2(v0, v1);
            }
        }
        __syncthreads();

        // GEMM2: P2 @ Wc
        zacc1(acc);
        hgemm1<16>(As_u, WC_u, wr, wc, gid, t4, acc);

        // epilogue2: m = tanh(acc + bc); H[dst] += m
#pragma unroll
        for (int h = 0; h < 2; ++h) {
            const int row = wr * 16 + gid + h * 8;
            float* hp = g_H + (size_t)s_dst[row] * DIM;
#pragma unroll
            for (int nb = 0; nb < 8; ++nb) {
                const int col = wc * 64 + nb * 8 + t4 * 2;
                float2 bb = __ldg((const float2*)(bc + col));
                float m0 = tanh_fast(acc[nb][2 * h + 0] + bb.x);
                float m1 = tanh_fast(acc[nb][2 * h + 1] + bb.y);
                red_add_v2(hp + col, m0, m1);
            }
        }
        __syncthreads();  // protect As / s_* before next tile
    }
}

// ---------------------------------------------------------------------------
// launch
// ---------------------------------------------------------------------------
extern "C" void kernel_launch(void* const* d_in, const int* in_sizes, int n_in,
                              void* d_out, int out_size) {
    const int wb = n_in - 16;
    const int*   node_types = (const int*)d_in[0];
    const int*   edge_types = (const int*)d_in[1];
    const int*   src        = (const int*)d_in[2];
    const int*   dst        = (const int*)d_in[3];
    const int*   graph_ids  = (const int*)d_in[4];
    const float* distances  = (const float*)d_in[5];
    const float* node_emb = (const float*)d_in[wb + 0];
    const float* edge_emb = (const float*)d_in[wb + 1];
    const float* Wn1 = (const float*)d_in[wb + 2];
    const float* bn1 = (const float*)d_in[wb + 3];
    const float* Wn2 = (const float*)d_in[wb + 4];
    const float* bn2 = (const float*)d_in[wb + 5];
    const float* We1 = (const float*)d_in[wb + 6];
    const float* be1 = (const float*)d_in[wb + 7];
    const float* We2 = (const float*)d_in[wb + 8];
    const float* be2 = (const float*)d_in[wb + 9];
    const float* Wc  = (const float*)d_in[wb + 10];
    const float* bc  = (const float*)d_in[wb + 11];
    const float* Wr1 = (const float*)d_in[wb + 12];
    const float* br1 = (const float*)d_in[wb + 13];
    const float* Wr2 = (const float*)d_in[wb + 14];
    const float* br2 = (const float*)d_in[wb + 15];
    float* out = (float*)d_out;

    const int TSM = TILE * LDA * 4;

    cudaFuncSetAttribute(k_edge_hmma,     cudaFuncAttributeMaxDynamicSharedMemorySize, ESMEM);
    cudaFuncSetAttribute(k_nodepath_hmma, cudaFuncAttributeMaxDynamicSharedMemorySize, NPSMEM);
    cudaFuncSetAttribute(k_readout_hmma,  cudaFuncAttributeMaxDynamicSharedMemorySize, ROSMEM);
    cudaFuncSetAttribute(k_t1,            cudaFuncAttributeMaxDynamicSharedMemorySize, TSM);

    k_zero<<<1, 128>>>(out, out_size);
    k_embed<<<(N_NODES * 32 + 255) / 256, 256>>>(node_types, node_emb);
    k_t1<<<dim3(4, 3), NTHREADS, TSM>>>(edge_emb, We1, be1);

    for (int i = 0; i < N_CONV; ++i) {
        k_nodepath_hmma<<<148, NTHREADS, NPSMEM>>>(
            Wn1 + (size_t)i * DIM * DIM, bn1 + (size_t)i * DIM,
            Wn2 + (size_t)i * DIM * DIM, bn2 + (size_t)i * DIM);
        k_edge_hmma<<<148, ETHREADS, ESMEM>>>(
            edge_types, src, dst, distances,
            We1 + (size_t)i * DIME * DIM + (size_t)DIM * DIM,
            We2 + (size_t)i * DIM * DIM, be2 + (size_t)i * DIM,
            Wc + (size_t)i * DIM * DIM, bc + (size_t)i * DIM, i);
    }

    k_readout_hmma<<<148, NTHREADS, ROSMEM>>>(
        graph_ids, Wr1, br1, Wr2, br2, out);
}

// round 7
// speedup vs baseline: 4.7342x; 1.1801x over previous
#include <cuda_runtime.h>
#include <math.h>
#include <stdint.h>

#define DIM      128
#define NCENT    30
#define DIME     158
#define N_NODES  50000
#define N_EDGES  800000
#define N_CONV   3
#define EVOCAB   500
#define LDA      132
#define TILE     128
#define NTHREADS 256
#define N_TILES  (N_EDGES / TILE)         // 6250
#define N_NTILES ((N_NODES + 127) / 128)  // 391

extern __shared__ __align__(1024) char smem_raw[];

__device__ __align__(256) float g_H[(size_t)N_NODES * DIM];
__device__ __align__(256) float g_NP[(size_t)N_NODES * DIM];
__device__ __align__(256) float g_T1[(size_t)N_CONV * 512 * DIM];

// ---------------------------------------------------------------------------
// helpers
// ---------------------------------------------------------------------------
__device__ __forceinline__ float to_tf32(float x) {
    float r; asm("cvt.rna.tf32.f32 %0, %1;" : "=f"(r) : "f"(x)); return r;
}

__device__ __forceinline__ float tanh_fast(float x) {
    float ax = fabsf(x);
    float e = __expf(-2.0f * ax);
    float t = __fdividef(1.0f - e, 1.0f + e);
    return copysignf(t, x);
}

__device__ __forceinline__ void red_add_v2(float* p, float a, float b) {
    asm volatile("red.global.add.v2.f32 [%0], {%1, %2};"
                 :: "l"(p), "f"(a), "f"(b) : "memory");
}

__device__ __forceinline__ void barpair(int id) {
    asm volatile("bar.sync %0, 64;" :: "r"(id) : "memory");
}

__device__ __forceinline__ void mma1688(float c[4], const uint32_t a[4],
                                        uint32_t b0, uint32_t b1) {
    asm volatile(
        "mma.sync.aligned.m16n8k8.row.col.f32.tf32.tf32.f32 "
        "{%0,%1,%2,%3}, {%4,%5,%6,%7}, {%8,%9}, {%0,%1,%2,%3};"
        : "+f"(c[0]), "+f"(c[1]), "+f"(c[2]), "+f"(c[3])
        : "r"(a[0]), "r"(a[1]), "r"(a[2]), "r"(a[3]), "r"(b0), "r"(b1));
}

// 32-row warp GEMM: acc[2][8][4] += A[wr rows 32][K] * W[K][wc cols 64]
template <int KSTEPS>
__device__ __forceinline__ void hgemm2(const uint32_t* __restrict__ As_u,
                                       const uint32_t* __restrict__ W_u,
                                       int wr, int wc, int gid, int t4,
                                       float acc[2][8][4]) {
#pragma unroll 2
    for (int ks = 0; ks < KSTEPS; ++ks) {
        const int k0 = ks * 8;
        uint32_t a[2][4];
#pragma unroll
        for (int mb = 0; mb < 2; ++mb) {
            const int r = wr * 32 + mb * 16 + gid;
            a[mb][0] = As_u[r * 132 + k0 + t4];
            a[mb][1] = As_u[(r + 8) * 132 + k0 + t4];
            a[mb][2] = As_u[r * 132 + k0 + t4 + 4];
            a[mb][3] = As_u[(r + 8) * 132 + k0 + t4 + 4];
        }
#pragma unroll
        for (int nb = 0; nb < 8; ++nb) {
            const int n = wc * 64 + nb * 8 + gid;
            const uint32_t b0 = W_u[(k0 + t4) * 136 + n];
            const uint32_t b1 = W_u[(k0 + t4 + 4) * 136 + n];
            mma1688(acc[0][nb], a[0], b0, b1);
            mma1688(acc[1][nb], a[1], b0, b1);
        }
    }
}

__device__ __forceinline__ void zacc2(float acc[2][8][4]) {
#pragma unroll
    for (int m = 0; m < 2; ++m)
#pragma unroll
        for (int n = 0; n < 8; ++n)
#pragma unroll
            for (int j = 0; j < 4; ++j) acc[m][n][j] = 0.f;
}

// ---------------------------------------------------------------------------
// FFMA helpers (k_t1 only)
// ---------------------------------------------------------------------------
__device__ __forceinline__ void zero_acc8(float acc[8][8]) {
#pragma unroll
    for (int i = 0; i < 8; ++i)
#pragma unroll
        for (int j = 0; j < 8; ++j) acc[i][j] = 0.f;
}

template <int K, int KW, int LD>
__device__ __forceinline__ void gemm_frag4(const float* __restrict__ As,
                                           const float* __restrict__ W,
                                           int r0, int c0, float acc[8][8]) {
#pragma unroll 2
    for (int k = 0; k < K; k += 4) {
        float4 a4[8];
#pragma unroll
        for (int i = 0; i < 8; ++i) a4[i] = *(const float4*)&As[(r0 + i) * LD + k];
        const float* a = (const float*)a4;
#pragma unroll
        for (int kk = 0; kk < 4; ++kk) {
            int kq = k + kk;
            float w[8];
            if (K == KW || kq < KW) {
                float4 w0 = __ldg((const float4*)(W + kq * DIM + c0));
                float4 w1 = __ldg((const float4*)(W + kq * DIM + c0 + 4));
                w[0] = w0.x; w[1] = w0.y; w[2] = w0.z; w[3] = w0.w;
                w[4] = w1.x; w[5] = w1.y; w[6] = w1.z; w[7] = w1.w;
            } else {
#pragma unroll
                for (int j = 0; j < 8; ++j) w[j] = 0.f;
            }
#pragma unroll
            for (int i = 0; i < 8; ++i)
#pragma unroll
                for (int j = 0; j < 8; ++j)
                    acc[i][j] = fmaf(a[i * 4 + kk], w[j], acc[i][j]);
        }
    }
}

// ---------------------------------------------------------------------------
// small kernels
// ---------------------------------------------------------------------------
__global__ void k_zero(float* out, int n) {
    int i = blockIdx.x * blockDim.x + threadIdx.x;
    if (i < n) out[i] = 0.f;
}

__global__ void k_embed(const int* __restrict__ nt, const float* __restrict__ emb) {
    int idx = blockIdx.x * blockDim.x + threadIdx.x;
    if (idx < N_NODES * 32) {
        int n = idx >> 5, q = idx & 31;
        ((float4*)g_H)[(size_t)n * 32 + q] =
            __ldg(((const float4*)emb) + (size_t)nt[n] * 32 + q);
    }
}

__global__ __launch_bounds__(NTHREADS) void k_t1(const float* __restrict__ edge_emb,
                                                 const float* __restrict__ We1_all,
                                                 const float* __restrict__ be1_all) {
    float* As = (float*)smem_raw;
    const int tid = threadIdx.x;
    const int layer = blockIdx.y;
    const int t0b = blockIdx.x * TILE;
    const float* We1 = We1_all + (size_t)layer * DIME * DIM;
    const float* be1 = be1_all + (size_t)layer * DIM;
    float* T1 = g_T1 + (size_t)layer * 512 * DIM;

    for (int idx = tid; idx < TILE * 32; idx += NTHREADS) {
        int r = idx >> 5, q = idx & 31;
        int row = t0b + r;
        float4 v = make_float4(0.f, 0.f, 0.f, 0.f);
        if (row < EVOCAB) v = __ldg(((const float4*)edge_emb) + (size_t)row * 32 + q);
        *(float4*)&As[r * LDA + q * 4] = v;
    }
    __syncthreads();
    const int tr = tid >> 4, tc = tid & 15;
    const int r0 = tr * 8, c0 = tc * 8;
    float acc[8][8];
    zero_acc8(acc);
    gemm_frag4<DIM, DIM, LDA>(As, We1, r0, c0, acc);
    float4 b0 = __ldg((const float4*)(be1 + c0));
    float4 b1 = __ldg((const float4*)(be1 + c0 + 4));
    float bb[8] = {b0.x, b0.y, b0.z, b0.w, b1.x, b1.y, b1.z, b1.w};
#pragma unroll
    for (int i = 0; i < 8; ++i) {
        int row = t0b + r0 + i;
        if (row < EVOCAB) {
            float* tp = T1 + (size_t)row * DIM + c0;
            *(float4*)tp       = make_float4(acc[i][0] + bb[0], acc[i][1] + bb[1],
                                             acc[i][2] + bb[2], acc[i][3] + bb[3]);
            *(float4*)(tp + 4) = make_float4(acc[i][4] + bb[4], acc[i][5] + bb[5],
                                             acc[i][6] + bb[6], acc[i][7] + bb[7]);
        }
    }
}

// ---------------------------------------------------------------------------
// Persistent HMMA node-path (pair-barrier version)
// smem floats: As 16896 | W1 17408 | W2 17408 -> 206848 B
// ---------------------------------------------------------------------------
#define NP_W1 16896
#define NP_W2 34304
#define NPSMEM 206848

__global__ __launch_bounds__(NTHREADS, 1) void k_nodepath_hmma(const float* __restrict__ Wn1,
                                                               const float* __restrict__ bn1,
                                                               const float* __restrict__ Wn2,
                                                               const float* __restrict__ bn2) {
    float* smf = (float*)smem_raw;
    float* Asf = smf;
    uint32_t* As_u = (uint32_t*)Asf;
    uint32_t* W1_u = (uint32_t*)(smf + NP_W1);
    uint32_t* W2_u = (uint32_t*)(smf + NP_W2);

    const int tid = threadIdx.x;
    const int wid = tid >> 5, lane = tid & 31;
    const int gid = lane >> 2, t4 = lane & 3;
    const int wr = wid >> 1, wc = wid & 1;
    const int barid = 1 + wr;

    for (int idx = tid; idx < 128 * 128; idx += NTHREADS) {
        int k = idx >> 7, n = idx & 127;
        ((float*)W1_u)[k * 136 + n] = to_tf32(__ldg(&Wn1[k * DIM + n]));
        ((float*)W2_u)[k * 136 + n] = to_tf32(__ldg(&Wn2[k * DIM + n]));
    }
    float2 vb1[8], vb2[8];
#pragma unroll
    for (int nb = 0; nb < 8; ++nb) {
        int col = wc * 64 + nb * 8 + t4 * 2;
        vb1[nb] = __ldg((const float2*)(bn1 + col));
        vb2[nb] = __ldg((const float2*)(bn2 + col));
    }
    __syncthreads();

    int rows[4];
    rows[0] = wr * 32 + gid;       rows[1] = wr * 32 + gid + 8;
    rows[2] = wr * 32 + 16 + gid;  rows[3] = wr * 32 + 16 + gid + 8;

    float acc[2][8][4];

    for (int tile = blockIdx.x; tile < N_NTILES; tile += gridDim.x) {
        const int n0 = tile * TILE;
        // load H: lane -> row, own col half
        {
            const int row = wr * 32 + lane;
            const int n = n0 + row;
            float* dstp = Asf + row * 132 + wc * 64;
            if (n < N_NODES) {
                const float* hp = g_H + (size_t)n * DIM + wc * 64;
#pragma unroll
                for (int q = 0; q < 16; ++q) {
                    float4 v = *(const float4*)(hp + q * 4);
                    v.x = to_tf32(v.x); v.y = to_tf32(v.y);
                    v.z = to_tf32(v.z); v.w = to_tf32(v.w);
                    *(float4*)(dstp + q * 4) = v;
                }
            } else {
#pragma unroll
                for (int q = 0; q < 16; ++q)
                    *(float4*)(dstp + q * 4) = make_float4(0.f, 0.f, 0.f, 0.f);
            }
        }
        barpair(barid);
        zacc2(acc);
        hgemm2<16>(As_u, W1_u, wr, wc, gid, t4, acc);
        barpair(barid);
        // relu(acc + bn1) -> tf32 -> As (own cols)
#pragma unroll
        for (int mb = 0; mb < 2; ++mb)
#pragma unroll
            for (int h = 0; h < 2; ++h) {
                const int row = rows[mb * 2 + h];
#pragma unroll
                for (int nb = 0; nb < 8; ++nb) {
                    const int col = wc * 64 + nb * 8 + t4 * 2;
                    float v0 = to_tf32(fmaxf(acc[mb][nb][2 * h + 0] + vb1[nb].x, 0.f));
                    float v1 = to_tf32(fmaxf(acc[mb][nb][2 * h + 1] + vb1[nb].y, 0.f));
                    *(float2*)(Asf + row * 132 + col) = make_float2(v0, v1);
                }
            }
        barpair(barid);
        zacc2(acc);
        hgemm2<16>(As_u, W2_u, wr, wc, gid, t4, acc);
        // NP store (global only)
#pragma unroll
        for (int mb = 0; mb < 2; ++mb)
#pragma unroll
            for (int h = 0; h < 2; ++h) {
                const int row = rows[mb * 2 + h];
                const int n = n0 + row;
                if (n < N_NODES) {
                    float* np = g_NP + (size_t)n * DIM;
#pragma unroll
                    for (int nb = 0; nb < 8; ++nb) {
                        const int col = wc * 64 + nb * 8 + t4 * 2;
                        *(float2*)(np + col) = make_float2(acc[mb][nb][2 * h + 0] + vb2[nb].x,
                                                           acc[mb][nb][2 * h + 1] + vb2[nb].y);
                    }
                }
            }
        barpair(barid);  // release As before next tile's H load
    }
}

// ---------------------------------------------------------------------------
// Persistent HMMA readout
// smem floats: As 16896 | W1 17408 -> 137216 B
// ---------------------------------------------------------------------------
#define RO_W1 16896
#define ROSMEM 137216

__global__ __launch_bounds__(NTHREADS, 1) void k_readout_hmma(const int* __restrict__ gids,
                                                              const float* __restrict__ Wr1,
                                                              const float* __restrict__ br1,
                                                              const float* __restrict__ Wr2,
                                                              const float* __restrict__ br2,
                                                              float* __restrict__ out) {
    float* smf = (float*)smem_raw;
    float* Asf = smf;
    uint32_t* As_u = (uint32_t*)Asf;
    uint32_t* W1_u = (uint32_t*)(smf + RO_W1);

    const int tid = threadIdx.x;
    const int wid = tid >> 5, lane = tid & 31;
    const int gid = lane >> 2, t4 = lane & 3;
    const int wr = wid >> 1, wc = wid & 1;
    const int barid = 1 + wr;

    for (int idx = tid; idx < 128 * 128; idx += NTHREADS) {
        int k = idx >> 7, n = idx & 127;
        ((float*)W1_u)[k * 136 + n] = to_tf32(__ldg(&Wr1[k * DIM + n]));
    }
    float2 vb1[8];
#pragma unroll
    for (int nb = 0; nb < 8; ++nb) {
        int col = wc * 64 + nb * 8 + t4 * 2;
        vb1[nb] = __ldg((const float2*)(br1 + col));
    }
    __syncthreads();

    int rows[4];
    rows[0] = wr * 32 + gid;       rows[1] = wr * 32 + gid + 8;
    rows[2] = wr * 32 + 16 + gid;  rows[3] = wr * 32 + 16 + gid + 8;

    float acc[2][8][4];

    for (int tile = blockIdx.x; tile < N_NTILES; tile += gridDim.x) {
        const int n0 = tile * TILE;
        {
            const int row = wr * 32 + lane;
            const int n = n0 + row;
            float* dstp = Asf + row * 132 + wc * 64;
            if (n < N_NODES) {
                const float* hp = g_H + (size_t)n * DIM + wc * 64;
#pragma unroll
                for (int q = 0; q < 16; ++q) {
                    float4 v = *(const float4*)(hp + q * 4);
                    v.x = to_tf32(v.x); v.y = to_tf32(v.y);
                    v.z = to_tf32(v.z); v.w = to_tf32(v.w);
                    *(float4*)(dstp + q * 4) = v;
                }
            } else {
#pragma unroll
                for (int q = 0; q < 16; ++q)
                    *(float4*)(dstp + q * 4) = make_float4(0.f, 0.f, 0.f, 0.f);
            }
        }
        barpair(barid);
        zacc2(acc);
        hgemm2<16>(As_u, W1_u, wr, wc, gid, t4, acc);
        barpair(barid);
        // relu(acc + br1) -> As (fp32, own cols)
#pragma unroll
        for (int mb = 0; mb < 2; ++mb)
#pragma unroll
            for (int h = 0; h < 2; ++h) {
                const int row = rows[mb * 2 + h];
#pragma unroll
                for (int nb = 0; nb < 8; ++nb) {
                    const int col = wc * 64 + nb * 8 + t4 * 2;
                    *(float2*)(Asf + row * 132 + col) =
                        make_float2(fmaxf(acc[mb][nb][2 * h + 0] + vb1[nb].x, 0.f),
                                    fmaxf(acc[mb][nb][2 * h + 1] + vb1[nb].y, 0.f));
                }
            }
        barpair(barid);
        // dot: wc==0 warp, lane -> row, full 128 cols
        if (wc == 0) {
            const int row = wr * 32 + lane;
            const int n = n0 + row;
            if (n < N_NODES) {
                float s = __ldg(&br2[0]);
#pragma unroll 8
                for (int c = 0; c < DIM; c += 4) {
                    float4 b = *(float4*)&Asf[row * 132 + c];
                    float4 w = __ldg((const float4*)(Wr2 + c));
                    s += b.x * w.x + b.y * w.y + b.z * w.z + b.w * w.w;
                }
                atomicAdd(&out[__ldg(&gids[n])], s);
            }
        }
        barpair(barid);  // release As
    }
}

// ---------------------------------------------------------------------------
// Persistent tf32 edge kernel — 256 threads, 8 warps as 4 free-running pairs.
// Pair (wr) = warps (2wr, 2wr+1); wc = wid&1. 6 pair barriers per tile.
// smem floats: As 16896 | W2 17408 | WC 17408 | WR 4352 -> 224256 B
// ---------------------------------------------------------------------------
#define F_W2  16896
#define F_WC  34304
#define F_WR  51712
#define ESMEM 224256

__global__ __launch_bounds__(NTHREADS, 1) void k_edge_hmma(const int* __restrict__ etype,
                                                           const int* __restrict__ esrc,
                                                           const int* __restrict__ edst,
                                                           const float* __restrict__ dist,
                                                           const float* __restrict__ We1rbf,
                                                           const float* __restrict__ We2,
                                                           const float* __restrict__ be2,
                                                           const float* __restrict__ Wc,
                                                           const float* __restrict__ bc,
                                                           int layer) {
    float* smf = (float*)smem_raw;
    float* Asf = smf;
    uint32_t* As_u = (uint32_t*)Asf;
    uint32_t* W2_u = (uint32_t*)(smf + F_W2);
    uint32_t* WC_u = (uint32_t*)(smf + F_WC);
    uint32_t* WR_u = (uint32_t*)(smf + F_WR);

    const int tid = threadIdx.x;
    const int wid = tid >> 5;
    const int lane = tid & 31;
    const int gid = lane >> 2;
    const int t4  = lane & 3;
    const int wr  = wid >> 1;    // pair id / row block (32 rows)
    const int wc  = wid & 1;     // col half (64 cols)
    const int barid = 1 + wr;

    for (int idx = tid; idx < 128 * 128; idx += NTHREADS) {
        int k = idx >> 7, n = idx & 127;
        ((float*)W2_u)[k * 136 + n] = to_tf32(__ldg(&We2[k * DIM + n]));
        ((float*)WC_u)[k * 136 + n] = to_tf32(__ldg(&Wc[k * DIM + n]));
    }
    for (int idx = tid; idx < 32 * 128; idx += NTHREADS) {
        int k = idx >> 7, n = idx & 127;
        ((float*)WR_u)[k * 136 + n] = (k < NCENT) ? to_tf32(__ldg(&We1rbf[k * DIM + n])) : 0.f;
    }
    float2 vbe2[8], vbc[8];
#pragma unroll
    for (int nb = 0; nb < 8; ++nb) {
        int col = wc * 64 + nb * 8 + t4 * 2;
        vbe2[nb] = __ldg((const float2*)(be2 + col));
        vbc[nb]  = __ldg((const float2*)(bc + col));
    }
    const float* T1 = g_T1 + (size_t)layer * 512 * DIM;
    __syncthreads();

    int rows[4];
    rows[0] = wr * 32 + gid;       rows[1] = wr * 32 + gid + 8;
    rows[2] = wr * 32 + 16 + gid;  rows[3] = wr * 32 + 16 + gid + 8;

    float acc[2][8][4];
    float2 pf[4][8];

    for (int tile = blockIdx.x; tile < N_TILES; tile += gridDim.x) {
        const int e0 = tile * TILE;

        // rbf: wc==0 warp fills cols [0,32) of the pair's 32 rows (lane -> row)
        if (wc == 0) {
            const int row = wr * 32 + lane;
            const float d = __ldg(&dist[e0 + row]);
#pragma unroll
            for (int j0 = 0; j0 < 32; j0 += 4) {
                float4 v;
                float* vv = (float*)&v;
#pragma unroll
                for (int u = 0; u < 4; ++u) {
                    int j = j0 + u;
                    float rv = 0.f;
                    if (j < NCENT) {
                        float t = d - (10.0f / 29.0f) * (float)j;
                        rv = to_tf32(__expf(-t * t * (29.0f / 10.0f)));
                    }
                    vv[u] = rv;
                }
                *(float4*)(Asf + row * 132 + j0) = v;
            }
        }
        // prefetch T1[type] (overlaps rbf + GEMM0)
#pragma unroll
        for (int rr = 0; rr < 4; ++rr) {
            const int ty = __ldg(&etype[e0 + rows[rr]]);
            const float* t1p = T1 + (size_t)ty * DIM + wc * 64 + t4 * 2;
#pragma unroll
            for (int nb = 0; nb < 8; ++nb)
                pf[rr][nb] = __ldg((const float2*)(t1p + nb * 8));
        }
        barpair(barid);

        // GEMM0: rbf @ We1rbf (K=32)
        zacc2(acc);
        hgemm2<4>(As_u, WR_u, wr, wc, gid, t4, acc);
        barpair(barid);

        // epi0: P1 = tf32(relu(acc + T1)) -> As own cols
#pragma unroll
        for (int mb = 0; mb < 2; ++mb)
#pragma unroll
            for (int h = 0; h < 2; ++h) {
                const int rr = mb * 2 + h;
                const int row = rows[rr];
#pragma unroll
                for (int nb = 0; nb < 8; ++nb) {
                    const int col = wc * 64 + nb * 8 + t4 * 2;
                    float v0 = to_tf32(fmaxf(acc[mb][nb][2 * h + 0] + pf[rr][nb].x, 0.f));
                    float v1 = to_tf32(fmaxf(acc[mb][nb][2 * h + 1] + pf[rr][nb].y, 0.f));
                    *(float2*)(Asf + row * 132 + col) = make_float2(v0, v1);
                }
            }
        // prefetch NP[src] (overlaps GEMM1)
#pragma unroll
        for (int rr = 0; rr < 4; ++rr) {
            const int sr = __ldg(&esrc[e0 + rows[rr]]);
            const float* npp = g_NP + (size_t)sr * DIM + wc * 64 + t4 * 2;
#pragma unroll
            for (int nb = 0; nb < 8; ++nb)
                pf[rr][nb] = __ldg((const float2*)(npp + nb * 8));
        }
        barpair(barid);

        // GEMM1: P1 @ We2
        zacc2(acc);
        hgemm2<16>(As_u, W2_u, wr, wc, gid, t4, acc);
        barpair(barid);

        // epi1: P2 = tf32((acc + be2) * NP) -> As own cols
#pragma unroll
        for (int mb = 0; mb < 2; ++mb)
#pragma unroll
            for (int h = 0; h < 2; ++h) {
                const int rr = mb * 2 + h;
                const int row = rows[rr];
#pragma unroll
                for (int nb = 0; nb < 8; ++nb) {
                    const int col = wc * 64 + nb * 8 + t4 * 2;
                    float v0 = to_tf32((acc[mb][nb][2 * h + 0] + vbe2[nb].x) * pf[rr][nb].x);
                    float v1 = to_tf32((acc[mb][nb][2 * h + 1] + vbe2[nb].y) * pf[rr][nb].y);
                    *(float2*)(Asf + row * 132 + col) = make_float2(v0, v1);
                }
            }
        barpair(barid);

        // GEMM2: P2 @ Wc
        zacc2(acc);
        hgemm2<16>(As_u, WC_u, wr, wc, gid, t4, acc);
        barpair(barid);  // release As for next tile

        // epi2: m = tanh(acc + bc); H[dst] += m
#pragma unroll
        for (int mb = 0; mb < 2; ++mb)
#pragma unroll
            for (int h = 0; h < 2; ++h) {
                const int rr = mb * 2 + h;
                const int ds = __ldg(&edst[e0 + rows[rr]]);
                float* hp = g_H + (size_t)ds * DIM;
#pragma unroll
                for (int nb = 0; nb < 8; ++nb) {
                    const int col = wc * 64 + nb * 8 + t4 * 2;
                    float m0 = tanh_fast(acc[mb][nb][2 * h + 0] + vbc[nb].x);
                    float m1 = tanh_fast(acc[mb][nb][2 * h + 1] + vbc[nb].y);
                    red_add_v2(hp + col, m0, m1);
                }
            }
    }
}

// ---------------------------------------------------------------------------
// launch
// ---------------------------------------------------------------------------
extern "C" void kernel_launch(void* const* d_in, const int* in_sizes, int n_in,
                              void* d_out, int out_size) {
    const int wb = n_in - 16;
    const int*   node_types = (const int*)d_in[0];
    const int*   edge_types = (const int*)d_in[1];
    const int*   src        = (const int*)d_in[2];
    const int*   dst        = (const int*)d_in[3];
    const int*   graph_ids  = (const int*)d_in[4];
    const float* distances  = (const float*)d_in[5];
    const float* node_emb = (const float*)d_in[wb + 0];
    const float* edge_emb = (const float*)d_in[wb + 1];
    const float* Wn1 = (const float*)d_in[wb + 2];
    const float* bn1 = (const float*)d_in[wb + 3];
    const float* Wn2 = (const float*)d_in[wb + 4];
    const float* bn2 = (const float*)d_in[wb + 5];
    const float* We1 = (const float*)d_in[wb + 6];
    const float* be1 = (const float*)d_in[wb + 7];
    const float* We2 = (const float*)d_in[wb + 8];
    const float* be2 = (const float*)d_in[wb + 9];
    const float* Wc  = (const float*)d_in[wb + 10];
    const float* bc  = (const float*)d_in[wb + 11];
    const float* Wr1 = (const float*)d_in[wb + 12];
    const float* br1 = (const float*)d_in[wb + 13];
    const float* Wr2 = (const float*)d_in[wb + 14];
    const float* br2 = (const float*)d_in[wb + 15];
    float* out = (float*)d_out;

    const int TSM = TILE * LDA * 4;

    cudaFuncSetAttribute(k_edge_hmma,     cudaFuncAttributeMaxDynamicSharedMemorySize, ESMEM);
    cudaFuncSetAttribute(k_nodepath_hmma, cudaFuncAttributeMaxDynamicSharedMemorySize, NPSMEM);
    cudaFuncSetAttribute(k_readout_hmma,  cudaFuncAttributeMaxDynamicSharedMemorySize, ROSMEM);
    cudaFuncSetAttribute(k_t1,            cudaFuncAttributeMaxDynamicSharedMemorySize, TSM);

    k_zero<<<1, 128>>>(out, out_size);
    k_embed<<<(N_NODES * 32 + 255) / 256, 256>>>(node_types, node_emb);
    k_t1<<<dim3(4, 3), NTHREADS, TSM>>>(edge_emb, We1, be1);

    for (int i = 0; i < N_CONV; ++i) {
        k_nodepath_hmma<<<148, NTHREADS, NPSMEM>>>(
            Wn1 + (size_t)i * DIM * DIM, bn1 + (size_t)i * DIM,
            Wn2 + (size_t)i * DIM * DIM, bn2 + (size_t)i * DIM);
        k_edge_hmma<<<148, NTHREADS, ESMEM>>>(
            edge_types, src, dst, distances,
            We1 + (size_t)i * DIME * DIM + (size_t)DIM * DIM,
            We2 + (size_t)i * DIM * DIM, be2 + (size_t)i * DIM,
            Wc + (size_t)i * DIM * DIM, bc + (size_t)i * DIM, i);
    }

    k_readout_hmma<<<148, NTHREADS, ROSMEM>>>(
        graph_ids, Wr1, br1, Wr2, br2, out);
}

// round 11
// speedup vs baseline: 4.8578x; 1.0261x over previous
#include <cuda_runtime.h>
#include <math.h>
#include <stdint.h>

#define DIM      128
#define NCENT    30
#define DIME     158
#define N_NODES  50000
#define N_EDGES  800000
#define N_CONV   3
#define EVOCAB   500
#define LDA      132
#define TILE     128
#define NTHREADS 256
#define N_TILES  (N_EDGES / TILE)         // 6250
#define N_NTILES ((N_NODES + 127) / 128)  // 391

extern __shared__ __align__(1024) char smem_raw[];

__device__ __align__(256) float g_H[(size_t)N_NODES * DIM];
__device__ __align__(256) float g_NP[(size_t)N_NODES * DIM];
__device__ __align__(256) float g_T1[(size_t)N_CONV * 512 * DIM];

// ---------------------------------------------------------------------------
// helpers
// ---------------------------------------------------------------------------
__device__ __forceinline__ float to_tf32(float x) {
    float r; asm("cvt.rna.tf32.f32 %0, %1;" : "=f"(r) : "f"(x)); return r;
}

__device__ __forceinline__ float tanh_fast(float x) {
    float ax = fabsf(x);
    float e = __expf(-2.0f * ax);
    float t = __fdividef(1.0f - e, 1.0f + e);
    return copysignf(t, x);
}

__device__ __forceinline__ void red_add_v2(float* p, float a, float b) {
    asm volatile("red.global.add.v2.f32 [%0], {%1, %2};"
                 :: "l"(p), "f"(a), "f"(b) : "memory");
}

__device__ __forceinline__ void barpair(int id) {
    asm volatile("bar.sync %0, 64;" :: "r"(id) : "memory");
}

__device__ __forceinline__ void mma1688(float c[4], const uint32_t a[4],
                                        uint32_t b0, uint32_t b1) {
    asm volatile(
        "mma.sync.aligned.m16n8k8.row.col.f32.tf32.tf32.f32 "
        "{%0,%1,%2,%3}, {%4,%5,%6,%7}, {%8,%9}, {%0,%1,%2,%3};"
        : "+f"(c[0]), "+f"(c[1]), "+f"(c[2]), "+f"(c[3])
        : "r"(a[0]), "r"(a[1]), "r"(a[2]), "r"(a[3]), "r"(b0), "r"(b1));
}

// B2 layout: float2 row (ks*4+t4), stride 132 float2; (.x,.y) = W[k], W[k+4],
// k = ks*8+t4. 132 mod 16 == 4 -> perfect 2-phase LDS.64.
template <int KSTEPS>
__device__ __forceinline__ void hgemm2(const uint32_t* __restrict__ As_u,
                                       const float2* __restrict__ B2,
                                       int wr, int wc, int gid, int t4,
                                       float acc[2][8][4]) {
#pragma unroll 2
    for (int ks = 0; ks < KSTEPS; ++ks) {
        const int k0 = ks * 8;
        uint32_t a[2][4];
#pragma unroll
        for (int mb = 0; mb < 2; ++mb) {
            const int r = wr * 32 + mb * 16 + gid;
            a[mb][0] = As_u[r * 132 + k0 + t4];
            a[mb][1] = As_u[(r + 8) * 132 + k0 + t4];
            a[mb][2] = As_u[r * 132 + k0 + t4 + 4];
            a[mb][3] = As_u[(r + 8) * 132 + k0 + t4 + 4];
        }
        const float2* brow = B2 + (ks * 4 + t4) * 132 + wc * 64 + gid;
#pragma unroll
        for (int nb = 0; nb < 8; ++nb) {
            float2 b = brow[nb * 8];
            mma1688(acc[0][nb], a[0], __float_as_uint(b.x), __float_as_uint(b.y));
            mma1688(acc[1][nb], a[1], __float_as_uint(b.x), __float_as_uint(b.y));
        }
    }
}

// GEMM0 with register-resident rbf A fragments (no smem A traffic).
__device__ __forceinline__ void hgemm0_rbf(const float d4[4],
                                           const float2* __restrict__ WR2,
                                           int wc, int gid, int t4,
                                           float acc[2][8][4]) {
#pragma unroll
    for (int ks = 0; ks < 4; ++ks) {
        uint32_t a[2][4];
        const int j0 = ks * 8 + t4;       // <= 27, always valid
        const int j1 = j0 + 4;            // may be >= NCENT
        const float c0 = (10.0f / 29.0f) * (float)j0;
        const float c1 = (10.0f / 29.0f) * (float)j1;
#pragma unroll
        for (int mb = 0; mb < 2; ++mb)
#pragma unroll
            for (int h = 0; h < 2; ++h) {
                const float d = d4[mb * 2 + h];
                float t0 = d - c0;
                float v0 = to_tf32(__expf(-t0 * t0 * (29.0f / 10.0f)));
                float v1 = 0.f;
                if (j1 < NCENT) {
                    float t1 = d - c1;
                    v1 = to_tf32(__expf(-t1 * t1 * (29.0f / 10.0f)));
                }
                a[mb][h]     = __float_as_uint(v0);
                a[mb][h + 2] = __float_as_uint(v1);
            }
        const float2* brow = WR2 + (ks * 4 + t4) * 132 + wc * 64 + gid;
#pragma unroll
        for (int nb = 0; nb < 8; ++nb) {
            float2 b = brow[nb * 8];
            mma1688(acc[0][nb], a[0], __float_as_uint(b.x), __float_as_uint(b.y));
            mma1688(acc[1][nb], a[1], __float_as_uint(b.x), __float_as_uint(b.y));
        }
    }
}

__device__ __forceinline__ void zacc2(float acc[2][8][4]) {
#pragma unroll
    for (int m = 0; m < 2; ++m)
#pragma unroll
        for (int n = 0; n < 8; ++n)
#pragma unroll
            for (int j = 0; j < 4; ++j) acc[m][n][j] = 0.f;
}

// stage a 128x128 weight into B2 layout (tf32)
__device__ __forceinline__ void stage_B2(float2* dst, const float* __restrict__ W, int tid) {
    for (int idx = tid; idx < 64 * 128; idx += NTHREADS) {
        int row = idx >> 7, n = idx & 127;
        int klo = (row >> 2) * 8 + (row & 3);
        dst[row * 132 + n] = make_float2(to_tf32(__ldg(&W[klo * DIM + n])),
                                         to_tf32(__ldg(&W[(klo + 4) * DIM + n])));
    }
}

// ---------------------------------------------------------------------------
// FFMA helpers (k_t1 only)
// ---------------------------------------------------------------------------
__device__ __forceinline__ void zero_acc8(float acc[8][8]) {
#pragma unroll
    for (int i = 0; i < 8; ++i)
#pragma unroll
        for (int j = 0; j < 8; ++j) acc[i][j] = 0.f;
}

template <int K, int KW, int LD>
__device__ __forceinline__ void gemm_frag4(const float* __restrict__ As,
                                           const float* __restrict__ W,
                                           int r0, int c0, float acc[8][8]) {
#pragma unroll 2
    for (int k = 0; k < K; k += 4) {
        float4 a4[8];
#pragma unroll
        for (int i = 0; i < 8; ++i) a4[i] = *(const float4*)&As[(r0 + i) * LD + k];
        const float* a = (const float*)a4;
#pragma unroll
        for (int kk = 0; kk < 4; ++kk) {
            int kq = k + kk;
            float w[8];
            if (K == KW || kq < KW) {
                float4 w0 = __ldg((const float4*)(W + kq * DIM + c0));
                float4 w1 = __ldg((const float4*)(W + kq * DIM + c0 + 4));
                w[0] = w0.x; w[1] = w0.y; w[2] = w0.z; w[3] = w0.w;
                w[4] = w1.x; w[5] = w1.y; w[6] = w1.z; w[7] = w1.w;
            } else {
#pragma unroll
                for (int j = 0; j < 8; ++j) w[j] = 0.f;
            }
#pragma unroll
            for (int i = 0; i < 8; ++i)
#pragma unroll
                for (int j = 0; j < 8; ++j)
                    acc[i][j] = fmaf(a[i * 4 + kk], w[j], acc[i][j]);
        }
    }
}

// ---------------------------------------------------------------------------
// small kernels
// ---------------------------------------------------------------------------
__global__ void k_zero(float* out, int n) {
    int i = blockIdx.x * blockDim.x + threadIdx.x;
    if (i < n) out[i] = 0.f;
}

__global__ void k_embed(const int* __restrict__ nt, const float* __restrict__ emb) {
    int idx = blockIdx.x * blockDim.x + threadIdx.x;
    if (idx < N_NODES * 32) {
        int n = idx >> 5, q = idx & 31;
        ((float4*)g_H)[(size_t)n * 32 + q] =
            __ldg(((const float4*)emb) + (size_t)nt[n] * 32 + q);
    }
}

__global__ __launch_bounds__(NTHREADS) void k_t1(const float* __restrict__ edge_emb,
                                                 const float* __restrict__ We1_all,
                                                 const float* __restrict__ be1_all) {
    float* As = (float*)smem_raw;
    const int tid = threadIdx.x;
    const int layer = blockIdx.y;
    const int t0b = blockIdx.x * TILE;
    const float* We1 = We1_all + (size_t)layer * DIME * DIM;
    const float* be1 = be1_all + (size_t)layer * DIM;
    float* T1 = g_T1 + (size_t)layer * 512 * DIM;

    for (int idx = tid; idx < TILE * 32; idx += NTHREADS) {
        int r = idx >> 5, q = idx & 31;
        int row = t0b + r;
        float4 v = make_float4(0.f, 0.f, 0.f, 0.f);
        if (row < EVOCAB) v = __ldg(((const float4*)edge_emb) + (size_t)row * 32 + q);
        *(float4*)&As[r * LDA + q * 4] = v;
    }
    __syncthreads();
    const int tr = tid >> 4, tc = tid & 15;
    const int r0 = tr * 8, c0 = tc * 8;
    float acc[8][8];
    zero_acc8(acc);
    gemm_frag4<DIM, DIM, LDA>(As, We1, r0, c0, acc);
    float4 b0 = __ldg((const float4*)(be1 + c0));
    float4 b1 = __ldg((const float4*)(be1 + c0 + 4));
    float bb[8] = {b0.x, b0.y, b0.z, b0.w, b1.x, b1.y, b1.z, b1.w};
#pragma unroll
    for (int i = 0; i < 8; ++i) {
        int row = t0b + r0 + i;
        if (row < EVOCAB) {
            float* tp = T1 + (size_t)row * DIM + c0;
            *(float4*)tp       = make_float4(acc[i][0] + bb[0], acc[i][1] + bb[1],
                                             acc[i][2] + bb[2], acc[i][3] + bb[3]);
            *(float4*)(tp + 4) = make_float4(acc[i][4] + bb[4], acc[i][5] + bb[5],
                                             acc[i][6] + bb[6], acc[i][7] + bb[7]);
        }
    }
}

// ---------------------------------------------------------------------------
// Persistent HMMA node-path (pair barriers, B2 layout)
// smem floats: As 16896 | W1 16896 | W2 16896 -> 202752 B
// ---------------------------------------------------------------------------
#define NP_W1 16896
#define NP_W2 33792
#define NPSMEM 202752

__global__ __launch_bounds__(NTHREADS, 1) void k_nodepath_hmma(const float* __restrict__ Wn1,
                                                               const float* __restrict__ bn1,
                                                               const float* __restrict__ Wn2,
                                                               const float* __restrict__ bn2) {
    float* smf = (float*)smem_raw;
    float* Asf = smf;
    uint32_t* As_u = (uint32_t*)Asf;
    float2* W1_2 = (float2*)(smf + NP_W1);
    float2* W2_2 = (float2*)(smf + NP_W2);

    const int tid = threadIdx.x;
    const int wid = tid >> 5, lane = tid & 31;
    const int gid = lane >> 2, t4 = lane & 3;
    const int wr = wid >> 1, wc = wid & 1;
    const int barid = 1 + wr;

    stage_B2(W1_2, Wn1, tid);
    stage_B2(W2_2, Wn2, tid);
    float2 vb1[8], vb2[8];
#pragma unroll
    for (int nb = 0; nb < 8; ++nb) {
        int col = wc * 64 + nb * 8 + t4 * 2;
        vb1[nb] = __ldg((const float2*)(bn1 + col));
        vb2[nb] = __ldg((const float2*)(bn2 + col));
    }
    __syncthreads();

    int rows[4];
    rows[0] = wr * 32 + gid;       rows[1] = wr * 32 + gid + 8;
    rows[2] = wr * 32 + 16 + gid;  rows[3] = wr * 32 + 16 + gid + 8;

    float acc[2][8][4];

    for (int tile = blockIdx.x; tile < N_NTILES; tile += gridDim.x) {
        const int n0 = tile * TILE;
        {
            const int row = wr * 32 + lane;
            const int n = n0 + row;
            float* dstp = Asf + row * 132 + wc * 64;
            if (n < N_NODES) {
                const float* hp = g_H + (size_t)n * DIM + wc * 64;
#pragma unroll
                for (int q = 0; q < 16; ++q) {
                    float4 v = *(const float4*)(hp + q * 4);
                    v.x = to_tf32(v.x); v.y = to_tf32(v.y);
                    v.z = to_tf32(v.z); v.w = to_tf32(v.w);
                    *(float4*)(dstp + q * 4) = v;
                }
            } else {
#pragma unroll
                for (int q = 0; q < 16; ++q)
                    *(float4*)(dstp + q * 4) = make_float4(0.f, 0.f, 0.f, 0.f);
            }
        }
        barpair(barid);
        zacc2(acc);
        hgemm2<16>(As_u, W1_2, wr, wc, gid, t4, acc);
        barpair(barid);
#pragma unroll
        for (int mb = 0; mb < 2; ++mb)
#pragma unroll
            for (int h = 0; h < 2; ++h) {
                const int row = rows[mb * 2 + h];
#pragma unroll
                for (int nb = 0; nb < 8; ++nb) {
                    const int col = wc * 64 + nb * 8 + t4 * 2;
                    float v0 = to_tf32(fmaxf(acc[mb][nb][2 * h + 0] + vb1[nb].x, 0.f));
                    float v1 = to_tf32(fmaxf(acc[mb][nb][2 * h + 1] + vb1[nb].y, 0.f));
                    *(float2*)(Asf + row * 132 + col) = make_float2(v0, v1);
                }
            }
        barpair(barid);
        zacc2(acc);
        hgemm2<16>(As_u, W2_2, wr, wc, gid, t4, acc);
#pragma unroll
        for (int mb = 0; mb < 2; ++mb)
#pragma unroll
            for (int h = 0; h < 2; ++h) {
                const int row = rows[mb * 2 + h];
                const int n = n0 + row;
                if (n < N_NODES) {
                    float* np = g_NP + (size_t)n * DIM;
#pragma unroll
                    for (int nb = 0; nb < 8; ++nb) {
                        const int col = wc * 64 + nb * 8 + t4 * 2;
                        *(float2*)(np + col) = make_float2(acc[mb][nb][2 * h + 0] + vb2[nb].x,
                                                           acc[mb][nb][2 * h + 1] + vb2[nb].y);
                    }
                }
            }
        barpair(barid);
    }
}

// ---------------------------------------------------------------------------
// Persistent HMMA readout (B2 layout)
// smem floats: As 16896 | W1 16896 -> 135168 B
// ---------------------------------------------------------------------------
#define RO_W1 16896
#define ROSMEM 135168

__global__ __launch_bounds__(NTHREADS, 1) void k_readout_hmma(const int* __restrict__ gids,
                                                              const float* __restrict__ Wr1,
                                                              const float* __restrict__ br1,
                                                              const float* __restrict__ Wr2,
                                                              const float* __restrict__ br2,
                                                              float* __restrict__ out) {
    float* smf = (float*)smem_raw;
    float* Asf = smf;
    uint32_t* As_u = (uint32_t*)Asf;
    float2* W1_2 = (float2*)(smf + RO_W1);

    const int tid = threadIdx.x;
    const int wid = tid >> 5, lane = tid & 31;
    const int gid = lane >> 2, t4 = lane & 3;
    const int wr = wid >> 1, wc = wid & 1;
    const int barid = 1 + wr;

    stage_B2(W1_2, Wr1, tid);
    float2 vb1[8];
#pragma unroll
    for (int nb = 0; nb < 8; ++nb) {
        int col = wc * 64 + nb * 8 + t4 * 2;
        vb1[nb] = __ldg((const float2*)(br1 + col));
    }
    __syncthreads();

    int rows[4];
    rows[0] = wr * 32 + gid;       rows[1] = wr * 32 + gid + 8;
    rows[2] = wr * 32 + 16 + gid;  rows[3] = wr * 32 + 16 + gid + 8;

    float acc[2][8][4];

    for (int tile = blockIdx.x; tile < N_NTILES; tile += gridDim.x) {
        const int n0 = tile * TILE;
        {
            const int row = wr * 32 + lane;
            const int n = n0 + row;
            float* dstp = Asf + row * 132 + wc * 64;
            if (n < N_NODES) {
                const float* hp = g_H + (size_t)n * DIM + wc * 64;
#pragma unroll
                for (int q = 0; q < 16; ++q) {
                    float4 v = *(const float4*)(hp + q * 4);
                    v.x = to_tf32(v.x); v.y = to_tf32(v.y);
                    v.z = to_tf32(v.z); v.w = to_tf32(v.w);
                    *(float4*)(dstp + q * 4) = v;
                }
            } else {
#pragma unroll
                for (int q = 0; q < 16; ++q)
                    *(float4*)(dstp + q * 4) = make_float4(0.f, 0.f, 0.f, 0.f);
            }
        }
        barpair(barid);
        zacc2(acc);
        hgemm2<16>(As_u, W1_2, wr, wc, gid, t4, acc);
        barpair(barid);
#pragma unroll
        for (int mb = 0; mb < 2; ++mb)
#pragma unroll
            for (int h = 0; h < 2; ++h) {
                const int row = rows[mb * 2 + h];
#pragma unroll
                for (int nb = 0; nb < 8; ++nb) {
                    const int col = wc * 64 + nb * 8 + t4 * 2;
                    *(float2*)(Asf + row * 132 + col) =
                        make_float2(fmaxf(acc[mb][nb][2 * h + 0] + vb1[nb].x, 0.f),
                                    fmaxf(acc[mb][nb][2 * h + 1] + vb1[nb].y, 0.f));
                }
            }
        barpair(barid);
        if (wc == 0) {
            const int row = wr * 32 + lane;
            const int n = n0 + row;
            if (n < N_NODES) {
                float s = __ldg(&br2[0]);
#pragma unroll 8
                for (int c = 0; c < DIM; c += 4) {
                    float4 b = *(float4*)&Asf[row * 132 + c];
                    float4 w = __ldg((const float4*)(Wr2 + c));
                    s += b.x * w.x + b.y * w.y + b.z * w.z + b.w * w.w;
                }
                atomicAdd(&out[__ldg(&gids[n])], s);
            }
        }
        barpair(barid);
    }
}

// ---------------------------------------------------------------------------
// Persistent tf32 edge kernel — 4 free-running warp pairs, 4 barriers/tile,
// register rbf, B2/LDS.64 weights.
// smem floats: As 16896 | W2 16896 | WC 16896 | WR 4224 -> 219648 B
// ---------------------------------------------------------------------------
#define F_W2  16896
#define F_WC  33792
#define F_WR  50688
#define ESMEM 219648

__global__ __launch_bounds__(NTHREADS, 1) void k_edge_hmma(const int* __restrict__ etype,
                                                           const int* __restrict__ esrc,
                                                           const int* __restrict__ edst,
                                                           const float* __restrict__ dist,
                                                           const float* __restrict__ We1rbf,
                                                           const float* __restrict__ We2,
                                                           const float* __restrict__ be2,
                                                           const float* __restrict__ Wc,
                                                           const float* __restrict__ bc,
                                                           int layer) {
    float* smf = (float*)smem_raw;
    float* Asf = smf;
    uint32_t* As_u = (uint32_t*)Asf;
    float2* W2_2 = (float2*)(smf + F_W2);
    float2* WC_2 = (float2*)(smf + F_WC);
    float2* WR_2 = (float2*)(smf + F_WR);

    const int tid = threadIdx.x;
    const int wid = tid >> 5;
    const int lane = tid & 31;
    const int gid = lane >> 2;
    const int t4  = lane & 3;
    const int wr  = wid >> 1;
    const int wc  = wid & 1;
    const int barid = 1 + wr;

    stage_B2(W2_2, We2, tid);
    stage_B2(WC_2, Wc, tid);
    for (int idx = tid; idx < 16 * 128; idx += NTHREADS) {
        int row = idx >> 7, n = idx & 127;
        int klo = (row >> 2) * 8 + (row & 3);
        int khi = klo + 4;
        float lo = to_tf32(__ldg(&We1rbf[klo * DIM + n]));
        float hi = (khi < NCENT) ? to_tf32(__ldg(&We1rbf[khi * DIM + n])) : 0.f;
        WR_2[row * 132 + n] = make_float2(lo, hi);
    }
    float2 vbe2[8], vbc[8];
#pragma unroll
    for (int nb = 0; nb < 8; ++nb) {
        int col = wc * 64 + nb * 8 + t4 * 2;
        vbe2[nb] = __ldg((const float2*)(be2 + col));
        vbc[nb]  = __ldg((const float2*)(bc + col));
    }
    const float* T1 = g_T1 + (size_t)layer * 512 * DIM;
    __syncthreads();

    int rows[4];
    rows[0] = wr * 32 + gid;       rows[1] = wr * 32 + gid + 8;
    rows[2] = wr * 32 + 16 + gid;  rows[3] = wr * 32 + 16 + gid + 8;

    float acc[2][8][4];
    float2 pf[4][8];

    for (int tile = blockIdx.x; tile < N_TILES; tile += gridDim.x) {
        const int e0 = tile * TILE;

        // d values for this thread's 4 rows (broadcast across t4 lanes)
        float d4[4];
#pragma unroll
        for (int rr = 0; rr < 4; ++rr)
            d4[rr] = __ldg(&dist[e0 + rows[rr]]);

        // prefetch T1[type] (overlaps GEMM0)
#pragma unroll
        for (int rr = 0; rr < 4; ++rr) {
            const int ty = __ldg(&etype[e0 + rows[rr]]);
            const float* t1p = T1 + (size_t)ty * DIM + wc * 64 + t4 * 2;
#pragma unroll
            for (int nb = 0; nb < 8; ++nb)
                pf[rr][nb] = __ldg((const float2*)(t1p + nb * 8));
        }

        // GEMM0: rbf (registers) @ We1rbf — no smem A traffic, no barrier needed
        zacc2(acc);
        hgemm0_rbf(d4, WR_2, wc, gid, t4, acc);

        // epi0: P1 = tf32(relu(acc + T1)) -> As own cols
        // (As free: release barrier of previous tile covers partner's GEMM2 reads)
#pragma unroll
        for (int mb = 0; mb < 2; ++mb)
#pragma unroll
            for (int h = 0; h < 2; ++h) {
                const int rr = mb * 2 + h;
                const int row = rows[rr];
#pragma unroll
                for (int nb = 0; nb < 8; ++nb) {
                    const int col = wc * 64 + nb * 8 + t4 * 2;
                    float v0 = to_tf32(fmaxf(acc[mb][nb][2 * h + 0] + pf[rr][nb].x, 0.f));
                    float v1 = to_tf32(fmaxf(acc[mb][nb][2 * h + 1] + pf[rr][nb].y, 0.f));
                    *(float2*)(Asf + row * 132 + col) = make_float2(v0, v1);
                }
            }
        // prefetch NP[src] (overlaps barrier + GEMM1)
#pragma unroll
        for (int rr = 0; rr < 4; ++rr) {
            const int sr = __ldg(&esrc[e0 + rows[rr]]);
            const float* npp = g_NP + (size_t)sr * DIM + wc * 64 + t4 * 2;
#pragma unroll
            for (int nb = 0; nb < 8; ++nb)
                pf[rr][nb] = __ldg((const float2*)(npp + nb * 8));
        }
        barpair(barid);  // P1 band complete (both halves)

        // GEMM1: P1 @ We2
        zacc2(acc);
        hgemm2<16>(As_u, W2_2, wr, wc, gid, t4, acc);
        barpair(barid);  // all GEMM1 A-reads done

        // epi1: P2 = tf32((acc + be2) * NP) -> As own cols
#pragma unroll
        for (int mb = 0; mb < 2; ++mb)
#pragma unroll
            for (int h = 0; h < 2; ++h) {
                const int rr = mb * 2 + h;
                const int row = rows[rr];
#pragma unroll
                for (int nb = 0; nb < 8; ++nb) {
                    const int col = wc * 64 + nb * 8 + t4 * 2;
                    float v0 = to_tf32((acc[mb][nb][2 * h + 0] + vbe2[nb].x) * pf[rr][nb].x);
                    float v1 = to_tf32((acc[mb][nb][2 * h + 1] + vbe2[nb].y) * pf[rr][nb].y);
                    *(float2*)(Asf + row * 132 + col) = make_float2(v0, v1);
                }
            }
        barpair(barid);  // P2 band complete

        // GEMM2: P2 @ Wc
        zacc2(acc);
        hgemm2<16>(As_u, WC_2, wr, wc, gid, t4, acc);
        barpair(barid);  // release As for next tile

        // epi2: m = tanh(acc + bc); H[dst] += m  (acc only; overlaps next tile)
#pragma unroll
        for (int mb = 0; mb < 2; ++mb)
#pragma unroll
            for (int h = 0; h < 2; ++h) {
                const int rr = mb * 2 + h;
                const int ds = __ldg(&edst[e0 + rows[rr]]);
                float* hp = g_H + (size_t)ds * DIM;
#pragma unroll
                for (int nb = 0; nb < 8; ++nb) {
                    const int col = wc * 64 + nb * 8 + t4 * 2;
                    float m0 = tanh_fast(acc[mb][nb][2 * h + 0] + vbc[nb].x);
                    float m1 = tanh_fast(acc[mb][nb][2 * h + 1] + vbc[nb].y);
                    red_add_v2(hp + col, m0, m1);
                }
            }
    }
}

// ---------------------------------------------------------------------------
// launch
// ---------------------------------------------------------------------------
extern "C" void kernel_launch(void* const* d_in, const int* in_sizes, int n_in,
                              void* d_out, int out_size) {
    const int wb = n_in - 16;
    const int*   node_types = (const int*)d_in[0];
    const int*   edge_types = (const int*)d_in[1];
    const int*   src        = (const int*)d_in[2];
    const int*   dst        = (const int*)d_in[3];
    const int*   graph_ids  = (const int*)d_in[4];
    const float* distances  = (const float*)d_in[5];
    const float* node_emb = (const float*)d_in[wb + 0];
    const float* edge_emb = (const float*)d_in[wb + 1];
    const float* Wn1 = (const float*)d_in[wb + 2];
    const float* bn1 = (const float*)d_in[wb + 3];
    const float* Wn2 = (const float*)d_in[wb + 4];
    const float* bn2 = (const float*)d_in[wb + 5];
    const float* We1 = (const float*)d_in[wb + 6];
    const float* be1 = (const float*)d_in[wb + 7];
    const float* We2 = (const float*)d_in[wb + 8];
    const float* be2 = (const float*)d_in[wb + 9];
    const float* Wc  = (const float*)d_in[wb + 10];
    const float* bc  = (const float*)d_in[wb + 11];
    const float* Wr1 = (const float*)d_in[wb + 12];
    const float* br1 = (const float*)d_in[wb + 13];
    const float* Wr2 = (const float*)d_in[wb + 14];
    const float* br2 = (const float*)d_in[wb + 15];
    float* out = (float*)d_out;

    const int TSM = TILE * LDA * 4;

    cudaFuncSetAttribute(k_edge_hmma,     cudaFuncAttributeMaxDynamicSharedMemorySize, ESMEM);
    cudaFuncSetAttribute(k_nodepath_hmma, cudaFuncAttributeMaxDynamicSharedMemorySize, NPSMEM);
    cudaFuncSetAttribute(k_readout_hmma,  cudaFuncAttributeMaxDynamicSharedMemorySize, ROSMEM);
    cudaFuncSetAttribute(k_t1,            cudaFuncAttributeMaxDynamicSharedMemorySize, TSM);

    k_zero<<<1, 128>>>(out, out_size);
    k_embed<<<(N_NODES * 32 + 255) / 256, 256>>>(node_types, node_emb);
    k_t1<<<dim3(4, 3), NTHREADS, TSM>>>(edge_emb, We1, be1);

    for (int i = 0; i < N_CONV; ++i) {
        k_nodepath_hmma<<<148, NTHREADS, NPSMEM>>>(
            Wn1 + (size_t)i * DIM * DIM, bn1 + (size_t)i * DIM,
            Wn2 + (size_t)i * DIM * DIM, bn2 + (size_t)i * DIM);
        k_edge_hmma<<<148, NTHREADS, ESMEM>>>(
            edge_types, src, dst, distances,
            We1 + (size_t)i * DIME * DIM + (size_t)DIM * DIM,
            We2 + (size_t)i * DIM * DIM, be2 + (size_t)i * DIM,
            Wc + (size_t)i * DIM * DIM, bc + (size_t)i * DIM, i);
    }

    k_readout_hmma<<<148, NTHREADS, ROSMEM>>>(
        graph_ids, Wr1, br1, Wr2, br2, out);
}

// round 14
// speedup vs baseline: 5.1652x; 1.0633x over previous
#include <cuda_runtime.h>
#include <math.h>
#include <stdint.h>

#define DIM      128
#define NCENT    30
#define DIME     158
#define N_NODES  50000
#define N_EDGES  800000
#define N_CONV   3
#define EVOCAB   500
#define LDA      132
#define TILE     128
#define NTHREADS 256
#define N_EUNITS (N_EDGES / 16)   // 50000
#define N_NUNITS (N_NODES / 16)   // 3125

extern __shared__ __align__(1024) char smem_raw[];

__device__ __align__(256) float g_H[(size_t)N_NODES * DIM];
__device__ __align__(256) float g_NP[(size_t)N_NODES * DIM];
__device__ __align__(256) float g_T1[(size_t)N_CONV * 512 * DIM];

// ---------------------------------------------------------------------------
// helpers
// ---------------------------------------------------------------------------
__device__ __forceinline__ float to_tf32(float x) {
    float r; asm("cvt.rna.tf32.f32 %0, %1;" : "=f"(r) : "f"(x)); return r;
}

__device__ __forceinline__ float tanh_fast(float x) {
    float ax = fabsf(x);
    float e = __expf(-2.0f * ax);
    float t = __fdividef(1.0f - e, 1.0f + e);
    return copysignf(t, x);
}

__device__ __forceinline__ void red_add_v2(float* p, float a, float b) {
    asm volatile("red.global.add.v2.f32 [%0], {%1, %2};"
                 :: "l"(p), "f"(a), "f"(b) : "memory");
}

__device__ __forceinline__ void mma1688(float c[4], const uint32_t a[4],
                                        uint32_t b0, uint32_t b1) {
    asm volatile(
        "mma.sync.aligned.m16n8k8.row.col.f32.tf32.tf32.f32 "
        "{%0,%1,%2,%3}, {%4,%5,%6,%7}, {%8,%9}, {%0,%1,%2,%3};"
        : "+f"(c[0]), "+f"(c[1]), "+f"(c[2]), "+f"(c[3])
        : "r"(a[0]), "r"(a[1]), "r"(a[2]), "r"(a[3]), "r"(b0), "r"(b1));
}

// Warp-independent GEMM: acc[16][4] += band[16 rows][K] * W[K][128 cols]
// band: 16x132 floats (warp-private). B2 layout: float2 row (ks*4+t4),
// stride 132 float2; (.x,.y) = W[k], W[k+4].
template <int KSTEPS>
__device__ __forceinline__ void hgemm_w(const uint32_t* __restrict__ band,
                                        const float2* __restrict__ B2,
                                        int gid, int t4, float acc[16][4]) {
#pragma unroll 2
    for (int ks = 0; ks < KSTEPS; ++ks) {
        const int k0 = ks * 8;
        uint32_t a[4];
        a[0] = band[gid * 132 + k0 + t4];
        a[1] = band[(gid + 8) * 132 + k0 + t4];
        a[2] = band[gid * 132 + k0 + t4 + 4];
        a[3] = band[(gid + 8) * 132 + k0 + t4 + 4];
        const float2* brow = B2 + (ks * 4 + t4) * 132 + gid;
#pragma unroll
        for (int nb = 0; nb < 16; ++nb) {
            float2 b = brow[nb * 8];
            mma1688(acc[nb], a, __float_as_uint(b.x), __float_as_uint(b.y));
        }
    }
}

// GEMM0 with register-resident rbf A fragments (no smem A traffic).
__device__ __forceinline__ void hgemm0_rbf_w(const float d2[2],
                                             const float2* __restrict__ WR2,
                                             int gid, int t4, float acc[16][4]) {
#pragma unroll
    for (int ks = 0; ks < 4; ++ks) {
        uint32_t a[4];
        const int j0 = ks * 8 + t4;       // <= 27
        const int j1 = j0 + 4;            // may be >= NCENT
        const float c0 = (10.0f / 29.0f) * (float)j0;
        const float c1 = (10.0f / 29.0f) * (float)j1;
#pragma unroll
        for (int h = 0; h < 2; ++h) {
            const float d = d2[h];
            float t0 = d - c0;
            float v0 = to_tf32(__expf(-t0 * t0 * (29.0f / 10.0f)));
            float v1 = 0.f;
            if (j1 < NCENT) {
                float t1 = d - c1;
                v1 = to_tf32(__expf(-t1 * t1 * (29.0f / 10.0f)));
            }
            a[h]     = __float_as_uint(v0);
            a[h + 2] = __float_as_uint(v1);
        }
        const float2* brow = WR2 + (ks * 4 + t4) * 132 + gid;
#pragma unroll
        for (int nb = 0; nb < 16; ++nb) {
            float2 b = brow[nb * 8];
            mma1688(acc[nb], a, __float_as_uint(b.x), __float_as_uint(b.y));
        }
    }
}

__device__ __forceinline__ void zacc_w(float acc[16][4]) {
#pragma unroll
    for (int n = 0; n < 16; ++n)
#pragma unroll
        for (int j = 0; j < 4; ++j) acc[n][j] = 0.f;
}

// stage a 128x128 weight into B2 layout (tf32)
__device__ __forceinline__ void stage_B2(float2* dst, const float* __restrict__ W, int tid) {
    for (int idx = tid; idx < 64 * 128; idx += NTHREADS) {
        int row = idx >> 7, n = idx & 127;
        int klo = (row >> 2) * 8 + (row & 3);
        dst[row * 132 + n] = make_float2(to_tf32(__ldg(&W[klo * DIM + n])),
                                         to_tf32(__ldg(&W[(klo + 4) * DIM + n])));
    }
}

// load 2 H rows (gid, gid+8 of unit) into warp band as tf32
__device__ __forceinline__ void load_h_band(float* bandf, int n0, int gid, int t4) {
#pragma unroll
    for (int h = 0; h < 2; ++h) {
        const float* hp = g_H + (size_t)(n0 + gid + 8 * h) * DIM;
        float* bp = bandf + (gid + 8 * h) * 132;
#pragma unroll
        for (int i = 0; i < 8; ++i) {
            const int c = t4 * 4 + i * 16;
            float4 v = *(const float4*)(hp + c);
            v.x = to_tf32(v.x); v.y = to_tf32(v.y);
            v.z = to_tf32(v.z); v.w = to_tf32(v.w);
            *(float4*)(bp + c) = v;
        }
    }
}

// ---------------------------------------------------------------------------
// FFMA helpers (k_t1 only)
// ---------------------------------------------------------------------------
__device__ __forceinline__ void zero_acc8(float acc[8][8]) {
#pragma unroll
    for (int i = 0; i < 8; ++i)
#pragma unroll
        for (int j = 0; j < 8; ++j) acc[i][j] = 0.f;
}

template <int K, int KW, int LD>
__device__ __forceinline__ void gemm_frag4(const float* __restrict__ As,
                                           const float* __restrict__ W,
                                           int r0, int c0, float acc[8][8]) {
#pragma unroll 2
    for (int k = 0; k < K; k += 4) {
        float4 a4[8];
#pragma unroll
        for (int i = 0; i < 8; ++i) a4[i] = *(const float4*)&As[(r0 + i) * LD + k];
        const float* a = (const float*)a4;
#pragma unroll
        for (int kk = 0; kk < 4; ++kk) {
            int kq = k + kk;
            float w[8];
            if (K == KW || kq < KW) {
                float4 w0 = __ldg((const float4*)(W + kq * DIM + c0));
                float4 w1 = __ldg((const float4*)(W + kq * DIM + c0 + 4));
                w[0] = w0.x; w[1] = w0.y; w[2] = w0.z; w[3] = w0.w;
                w[4] = w1.x; w[5] = w1.y; w[6] = w1.z; w[7] = w1.w;
            } else {
#pragma unroll
                for (int j = 0; j < 8; ++j) w[j] = 0.f;
            }
#pragma unroll
            for (int i = 0; i < 8; ++i)
#pragma unroll
                for (int j = 0; j < 8; ++j)
                    acc[i][j] = fmaf(a[i * 4 + kk], w[j], acc[i][j]);
        }
    }
}

// ---------------------------------------------------------------------------
// small kernels
// ---------------------------------------------------------------------------
__global__ void k_zero(float* out, int n) {
    int i = blockIdx.x * blockDim.x + threadIdx.x;
    if (i < n) out[i] = 0.f;
}

__global__ void k_embed(const int* __restrict__ nt, const float* __restrict__ emb) {
    int idx = blockIdx.x * blockDim.x + threadIdx.x;
    if (idx < N_NODES * 32) {
        int n = idx >> 5, q = idx & 31;
        ((float4*)g_H)[(size_t)n * 32 + q] =
            __ldg(((const float4*)emb) + (size_t)nt[n] * 32 + q);
    }
}

__global__ __launch_bounds__(NTHREADS) void k_t1(const float* __restrict__ edge_emb,
                                                 const float* __restrict__ We1_all,
                                                 const float* __restrict__ be1_all) {
    float* As = (float*)smem_raw;
    const int tid = threadIdx.x;
    const int layer = blockIdx.y;
    const int t0b = blockIdx.x * TILE;
    const float* We1 = We1_all + (size_t)layer * DIME * DIM;
    const float* be1 = be1_all + (size_t)layer * DIM;
    float* T1 = g_T1 + (size_t)layer * 512 * DIM;

    for (int idx = tid; idx < TILE * 32; idx += NTHREADS) {
        int r = idx >> 5, q = idx & 31;
        int row = t0b + r;
        float4 v = make_float4(0.f, 0.f, 0.f, 0.f);
        if (row < EVOCAB) v = __ldg(((const float4*)edge_emb) + (size_t)row * 32 + q);
        *(float4*)&As[r * LDA + q * 4] = v;
    }
    __syncthreads();
    const int tr = tid >> 4, tc = tid & 15;
    const int r0 = tr * 8, c0 = tc * 8;
    float acc[8][8];
    zero_acc8(acc);
    gemm_frag4<DIM, DIM, LDA>(As, We1, r0, c0, acc);
    float4 b0 = __ldg((const float4*)(be1 + c0));
    float4 b1 = __ldg((const float4*)(be1 + c0 + 4));
    float bb[8] = {b0.x, b0.y, b0.z, b0.w, b1.x, b1.y, b1.z, b1.w};
#pragma unroll
    for (int i = 0; i < 8; ++i) {
        int row = t0b + r0 + i;
        if (row < EVOCAB) {
            float* tp = T1 + (size_t)row * DIM + c0;
            *(float4*)tp       = make_float4(acc[i][0] + bb[0], acc[i][1] + bb[1],
                                             acc[i][2] + bb[2], acc[i][3] + bb[3]);
            *(float4*)(tp + 4) = make_float4(acc[i][4] + bb[4], acc[i][5] + bb[5],
                                             acc[i][6] + bb[6], acc[i][7] + bb[7]);
        }
    }
}

// ---------------------------------------------------------------------------
// Warp-independent HMMA node-path: zero barriers in main loop.
// smem floats: As 16896 | W1 16896 | W2 16896 | sb1 128 | sb2 128 -> 203776 B
// ---------------------------------------------------------------------------
#define NP_W1 16896
#define NP_W2 33792
#define NP_B1 50688
#define NP_B2 50816
#define NPSMEM 203776

__global__ __launch_bounds__(NTHREADS, 1) void k_nodepath_hmma(const float* __restrict__ Wn1,
                                                               const float* __restrict__ bn1,
                                                               const float* __restrict__ Wn2,
                                                               const float* __restrict__ bn2) {
    float* smf = (float*)smem_raw;
    float2* W1_2 = (float2*)(smf + NP_W1);
    float2* W2_2 = (float2*)(smf + NP_W2);
    float* sb1 = smf + NP_B1;
    float* sb2 = smf + NP_B2;

    const int tid = threadIdx.x;
    const int wid = tid >> 5, lane = tid & 31;
    const int gid = lane >> 2, t4 = lane & 3;

    stage_B2(W1_2, Wn1, tid);
    stage_B2(W2_2, Wn2, tid);
    if (tid < 128) { sb1[tid] = __ldg(&bn1[tid]); sb2[tid] = __ldg(&bn2[tid]); }
    __syncthreads();

    float* bandf = smf + wid * 16 * 132;
    uint32_t* band = (uint32_t*)bandf;
    float acc[16][4];

    for (int u = blockIdx.x * 8 + wid; u < N_NUNITS; u += 148 * 8) {
        const int n0 = u * 16;
        load_h_band(bandf, n0, gid, t4);

        zacc_w(acc);
        hgemm_w<16>(band, W1_2, gid, t4, acc);

        // relu(acc + bn1) -> tf32 -> band
#pragma unroll
        for (int h = 0; h < 2; ++h) {
            float* bp = bandf + (gid + 8 * h) * 132;
#pragma unroll
            for (int nb = 0; nb < 16; ++nb) {
                const int col = nb * 8 + t4 * 2;
                float2 bb = *(const float2*)(sb1 + col);
                float v0 = to_tf32(fmaxf(acc[nb][2 * h + 0] + bb.x, 0.f));
                float v1 = to_tf32(fmaxf(acc[nb][2 * h + 1] + bb.y, 0.f));
                *(float2*)(bp + col) = make_float2(v0, v1);
            }
        }

        zacc_w(acc);
        hgemm_w<16>(band, W2_2, gid, t4, acc);

        // NP = acc + bn2
#pragma unroll
        for (int h = 0; h < 2; ++h) {
            float* np = g_NP + (size_t)(n0 + gid + 8 * h) * DIM;
#pragma unroll
            for (int nb = 0; nb < 16; ++nb) {
                const int col = nb * 8 + t4 * 2;
                float2 bb = *(const float2*)(sb2 + col);
                *(float2*)(np + col) = make_float2(acc[nb][2 * h + 0] + bb.x,
                                                   acc[nb][2 * h + 1] + bb.y);
            }
        }
    }
}

// ---------------------------------------------------------------------------
// Warp-independent HMMA readout: dot computed straight from acc + shfl reduce.
// smem floats: As 16896 | W1 16896 | sb1 128 | sw2 128 -> 136192 B
// ---------------------------------------------------------------------------
#define RO_W1 16896
#define RO_B1 33792
#define RO_W2 33920
#define ROSMEM 136192

__global__ __launch_bounds__(NTHREADS, 1) void k_readout_hmma(const int* __restrict__ gids,
                                                              const float* __restrict__ Wr1,
                                                              const float* __restrict__ br1,
                                                              const float* __restrict__ Wr2,
                                                              const float* __restrict__ br2,
                                                              float* __restrict__ out) {
    float* smf = (float*)smem_raw;
    float2* W1_2 = (float2*)(smf + RO_W1);
    float* sb1 = smf + RO_B1;
    float* sw2 = smf + RO_W2;

    const int tid = threadIdx.x;
    const int wid = tid >> 5, lane = tid & 31;
    const int gid = lane >> 2, t4 = lane & 3;

    stage_B2(W1_2, Wr1, tid);
    if (tid < 128) { sb1[tid] = __ldg(&br1[tid]); sw2[tid] = __ldg(&Wr2[tid]); }
    __syncthreads();
    const float b2v = __ldg(&br2[0]);

    float* bandf = smf + wid * 16 * 132;
    uint32_t* band = (uint32_t*)bandf;
    float acc[16][4];

    for (int u = blockIdx.x * 8 + wid; u < N_NUNITS; u += 148 * 8) {
        const int n0 = u * 16;
        load_h_band(bandf, n0, gid, t4);

        zacc_w(acc);
        hgemm_w<16>(band, W1_2, gid, t4, acc);

        // dot: p[h] = sum over this thread's cols of relu(acc+br1)*Wr2
        float p[2] = {0.f, 0.f};
#pragma unroll
        for (int nb = 0; nb < 16; ++nb) {
            const int col = nb * 8 + t4 * 2;
            float2 bb = *(const float2*)(sb1 + col);
            float2 ww = *(const float2*)(sw2 + col);
#pragma unroll
            for (int h = 0; h < 2; ++h) {
                p[h] += fmaxf(acc[nb][2 * h + 0] + bb.x, 0.f) * ww.x
                      + fmaxf(acc[nb][2 * h + 1] + bb.y, 0.f) * ww.y;
            }
        }
        // reduce over t4 group (lanes gid*4 + t4)
#pragma unroll
        for (int h = 0; h < 2; ++h) {
            p[h] += __shfl_xor_sync(0xffffffff, p[h], 1);
            p[h] += __shfl_xor_sync(0xffffffff, p[h], 2);
        }
        if (t4 == 0) {
            atomicAdd(&out[__ldg(&gids[n0 + gid])], p[0] + b2v);
            atomicAdd(&out[__ldg(&gids[n0 + gid + 8])], p[1] + b2v);
        }
    }
}

// ---------------------------------------------------------------------------
// Warp-independent tf32 edge kernel — 8 decoupled chains, ZERO barriers.
// Each warp owns a 16-edge unit: 16x132 A band + full 128 output cols.
// smem floats: As 16896 | W2 16896 | WC 16896 | WR 4224 | sbe2 128 | sbc 128
//   -> 55168 floats = 220672 B
// ---------------------------------------------------------------------------
#define F_W2  16896
#define F_WC  33792
#define F_WR  50688
#define F_BE2 54912
#define F_BC  55040
#define ESMEM 220672

__global__ __launch_bounds__(NTHREADS, 1) void k_edge_hmma(const int* __restrict__ etype,
                                                           const int* __restrict__ esrc,
                                                           const int* __restrict__ edst,
                                                           const float* __restrict__ dist,
                                                           const float* __restrict__ We1rbf,
                                                           const float* __restrict__ We2,
                                                           const float* __restrict__ be2,
                                                           const float* __restrict__ Wc,
                                                           const float* __restrict__ bc,
                                                           int layer) {
    float* smf = (float*)smem_raw;
    float2* W2_2 = (float2*)(smf + F_W2);
    float2* WC_2 = (float2*)(smf + F_WC);
    float2* WR_2 = (float2*)(smf + F_WR);
    float* sbe2 = smf + F_BE2;
    float* sbc  = smf + F_BC;

    const int tid = threadIdx.x;
    const int wid = tid >> 5;
    const int lane = tid & 31;
    const int gid = lane >> 2;
    const int t4  = lane & 3;

    stage_B2(W2_2, We2, tid);
    stage_B2(WC_2, Wc, tid);
    for (int idx = tid; idx < 16 * 128; idx += NTHREADS) {
        int row = idx >> 7, n = idx & 127;
        int klo = (row >> 2) * 8 + (row & 3);
        int khi = klo + 4;
        float lo = to_tf32(__ldg(&We1rbf[klo * DIM + n]));
        float hi = (khi < NCENT) ? to_tf32(__ldg(&We1rbf[khi * DIM + n])) : 0.f;
        WR_2[row * 132 + n] = make_float2(lo, hi);
    }
    if (tid < 128) { sbe2[tid] = __ldg(&be2[tid]); sbc[tid] = __ldg(&bc[tid]); }
    const float* T1 = g_T1 + (size_t)layer * 512 * DIM;
    __syncthreads();

    float* bandf = smf + wid * 16 * 132;
    uint32_t* band = (uint32_t*)bandf;

    float acc[16][4];
    float2 pf[2][16];

    for (int u = blockIdx.x * 8 + wid; u < N_EUNITS; u += 148 * 8) {
        const int e0 = u * 16;

        float d2[2];
        d2[0] = __ldg(&dist[e0 + gid]);
        d2[1] = __ldg(&dist[e0 + gid + 8]);

        // prefetch T1[type] for this thread's 2 rows (overlaps GEMM0)
#pragma unroll
        for (int h = 0; h < 2; ++h) {
            const int ty = __ldg(&etype[e0 + gid + 8 * h]);
            const float* t1p = T1 + (size_t)ty * DIM + t4 * 2;
#pragma unroll
            for (int nb = 0; nb < 16; ++nb)
                pf[h][nb] = __ldg((const float2*)(t1p + nb * 8));
        }

        // GEMM0: rbf (registers) @ We1rbf
        zacc_w(acc);
        hgemm0_rbf_w(d2, WR_2, gid, t4, acc);

        // epi0: P1 = tf32(relu(acc + T1)) -> band
#pragma unroll
        for (int h = 0; h < 2; ++h) {
            float* bp = bandf + (gid + 8 * h) * 132;
#pragma unroll
            for (int nb = 0; nb < 16; ++nb) {
                const int col = nb * 8 + t4 * 2;
                float v0 = to_tf32(fmaxf(acc[nb][2 * h + 0] + pf[h][nb].x, 0.f));
                float v1 = to_tf32(fmaxf(acc[nb][2 * h + 1] + pf[h][nb].y, 0.f));
                *(float2*)(bp + col) = make_float2(v0, v1);
            }
        }

        // prefetch NP[src] (overlaps GEMM1)
#pragma unroll
        for (int h = 0; h < 2; ++h) {
            const int sr = __ldg(&esrc[e0 + gid + 8 * h]);
            const float* npp = g_NP + (size_t)sr * DIM + t4 * 2;
#pragma unroll
            for (int nb = 0; nb < 16; ++nb)
                pf[h][nb] = __ldg((const float2*)(npp + nb * 8));
        }

        // GEMM1: P1 @ We2
        zacc_w(acc);
        hgemm_w<16>(band, W2_2, gid, t4, acc);

        // epi1: P2 = tf32((acc + be2) * NP) -> band
#pragma unroll
        for (int h = 0; h < 2; ++h) {
            float* bp = bandf + (gid + 8 * h) * 132;
#pragma unroll
            for (int nb = 0; nb < 16; ++nb) {
                const int col = nb * 8 + t4 * 2;
                float2 bb = *(const float2*)(sbe2 + col);
                float v0 = to_tf32((acc[nb][2 * h + 0] + bb.x) * pf[h][nb].x);
                float v1 = to_tf32((acc[nb][2 * h + 1] + bb.y) * pf[h][nb].y);
                *(float2*)(bp + col) = make_float2(v0, v1);
            }
        }

        // GEMM2: P2 @ Wc
        zacc_w(acc);
        hgemm_w<16>(band, WC_2, gid, t4, acc);

        // epi2: m = tanh(acc + bc); H[dst] += m
#pragma unroll
        for (int h = 0; h < 2; ++h) {
            const int ds = __ldg(&edst[e0 + gid + 8 * h]);
            float* hp = g_H + (size_t)ds * DIM;
#pragma unroll
            for (int nb = 0; nb < 16; ++nb) {
                const int col = nb * 8 + t4 * 2;
                float2 bb = *(const float2*)(sbc + col);
                float m0 = tanh_fast(acc[nb][2 * h + 0] + bb.x);
                float m1 = tanh_fast(acc[nb][2 * h + 1] + bb.y);
                red_add_v2(hp + col, m0, m1);
            }
        }
    }
}

// ---------------------------------------------------------------------------
// launch
// ---------------------------------------------------------------------------
extern "C" void kernel_launch(void* const* d_in, const int* in_sizes, int n_in,
                              void* d_out, int out_size) {
    const int wb = n_in - 16;
    const int*   node_types = (const int*)d_in[0];
    const int*   edge_types = (const int*)d_in[1];
    const int*   src        = (const int*)d_in[2];
    const int*   dst        = (const int*)d_in[3];
    const int*   graph_ids  = (const int*)d_in[4];
    const float* distances  = (const float*)d_in[5];
    const float* node_emb = (const float*)d_in[wb + 0];
    const float* edge_emb = (const float*)d_in[wb + 1];
    const float* Wn1 = (const float*)d_in[wb + 2];
    const float* bn1 = (const float*)d_in[wb + 3];
    const float* Wn2 = (const float*)d_in[wb + 4];
    const float* bn2 = (const float*)d_in[wb + 5];
    const float* We1 = (const float*)d_in[wb + 6];
    const float* be1 = (const float*)d_in[wb + 7];
    const float* We2 = (const float*)d_in[wb + 8];
    const float* be2 = (const float*)d_in[wb + 9];
    const float* Wc  = (const float*)d_in[wb + 10];
    const float* bc  = (const float*)d_in[wb + 11];
    const float* Wr1 = (const float*)d_in[wb + 12];
    const float* br1 = (const float*)d_in[wb + 13];
    const float* Wr2 = (const float*)d_in[wb + 14];
    const float* br2 = (const float*)d_in[wb + 15];
    float* out = (float*)d_out;

    const int TSM = TILE * LDA * 4;

    cudaFuncSetAttribute(k_edge_hmma,     cudaFuncAttributeMaxDynamicSharedMemorySize, ESMEM);
    cudaFuncSetAttribute(k_nodepath_hmma, cudaFuncAttributeMaxDynamicSharedMemorySize, NPSMEM);
    cudaFuncSetAttribute(k_readout_hmma,  cudaFuncAttributeMaxDynamicSharedMemorySize, ROSMEM);
    cudaFuncSetAttribute(k_t1,            cudaFuncAttributeMaxDynamicSharedMemorySize, TSM);

    k_zero<<<1, 128>>>(out, out_size);
    k_embed<<<(N_NODES * 32 + 255) / 256, 256>>>(node_types, node_emb);
    k_t1<<<dim3(4, 3), NTHREADS, TSM>>>(edge_emb, We1, be1);

    for (int i = 0; i < N_CONV; ++i) {
        k_nodepath_hmma<<<148, NTHREADS, NPSMEM>>>(
            Wn1 + (size_t)i * DIM * DIM, bn1 + (size_t)i * DIM,
            Wn2 + (size_t)i * DIM * DIM, bn2 + (size_t)i * DIM);
        k_edge_hmma<<<148, NTHREADS, ESMEM>>>(
            edge_types, src, dst, distances,
            We1 + (size_t)i * DIME * DIM + (size_t)DIM * DIM,
            We2 + (size_t)i * DIM * DIM, be2 + (size_t)i * DIM,
            Wc + (size_t)i * DIM * DIM, bc + (size_t)i * DIM, i);
    }

    k_readout_hmma<<<148, NTHREADS, ROSMEM>>>(
        graph_ids, Wr1, br1, Wr2, br2, out);
}